// round 10
// baseline (speedup 1.0000x reference)
#include <cuda_runtime.h>
#include <cuda_fp16.h>
#include <math.h>
#include <stdint.h>

#define D_MODEL 1024
#define D_INNER 2048
#define D_STATE 16
#define DT_RANK 64
#define NB 2
#define LSEQ 2048
#define BL (NB*LSEQ)            /* 4096 rows total */
#define XDBL_W 96
#define SPLITK 8

// ---------------- scratch (device globals) ----------------
__device__ float  g_h[(size_t)BL * D_MODEL];            // fp32: pre-LN
__device__ float  g_part[(size_t)SPLITK * BL * XDBL_W]; // split-K partials
// fp16 buffers (16B-aligned for cp.async)
__device__ __align__(16) __half g_xzh[(size_t)BL * 2 * D_INNER];
__device__ __align__(16) __half g_deltah[(size_t)BL * D_INNER];
__device__ __align__(16) __half g_uh[(size_t)BL * D_INNER];
__device__ __align__(16) __half g_xdbl_h[(size_t)BL * XDBL_W];
__device__ __align__(16) __half g_yh[(size_t)BL * D_INNER];
__device__ __align__(16) __half g_xh[(size_t)BL * D_MODEL];
__device__ __align__(16) __half g_w1h[(size_t)2 * D_INNER * D_MODEL];
__device__ __align__(16) __half g_w3h[(size_t)XDBL_W * D_INNER];
__device__ __align__(16) __half g_w4h[(size_t)D_INNER * DT_RANK];
__device__ __align__(16) __half g_w6h[(size_t)D_MODEL * D_INNER];

__device__ __forceinline__ void mma_f16(float* d, const uint32_t* a, const uint32_t* b) {
    asm volatile(
        "mma.sync.aligned.m16n8k16.row.col.f32.f16.f16.f32 "
        "{%0,%1,%2,%3}, {%4,%5,%6,%7}, {%8,%9}, {%0,%1,%2,%3};"
        : "+f"(d[0]), "+f"(d[1]), "+f"(d[2]), "+f"(d[3])
        : "r"(a[0]), "r"(a[1]), "r"(a[2]), "r"(a[3]), "r"(b[0]), "r"(b[1]));
}
__device__ __forceinline__ void ldsm4(uint32_t* r, uint32_t addr) {
    asm volatile("ldmatrix.sync.aligned.m8n8.x4.shared.b16 {%0,%1,%2,%3}, [%4];"
                 : "=r"(r[0]), "=r"(r[1]), "=r"(r[2]), "=r"(r[3]) : "r"(addr));
}
__device__ __forceinline__ void cp16(uint32_t dst, const void* src, bool pred) {
    int sz = pred ? 16 : 0;
    asm volatile("cp.async.cg.shared.global [%0], [%1], 16, %2;"
                 :: "r"(dst), "l"(src), "r"(sz) : "memory");
}
#define CP_COMMIT() asm volatile("cp.async.commit_group;" ::: "memory")
#define CP_WAIT(n)  asm volatile("cp.async.wait_group %0;" :: "n"(n) : "memory")

// ================= fp16 mma.sync GEMM (R7, unchanged — control) =================
#define SPITCH_H 40
#define A_HALVES (128 * SPITCH_H)
#define STAGE_HALVES (2 * A_HALVES)
#define STAGEB (STAGE_HALVES * 2)
#define NSTAGE 4

template<int EPI, typename OutT>
__global__ __launch_bounds__(256, 2)
void gemm_h(const __half* __restrict__ A, int lda,
            const __half* __restrict__ Bw, int ldb, int Nact,
            OutT* __restrict__ C, int ldc,
            const float* __restrict__ aux, int K, size_t csplit)
{
    extern __shared__ __half smem[];
    const int tid = threadIdx.x;
    const int wid = tid >> 5;
    const int lane = tid & 31;
    const int g = lane >> 2;
    const int t4 = lane & 3;
    const int warp_m = wid >> 1;
    const int warp_n = wid & 1;
    const int bm = blockIdx.y * 128;
    const int bn = blockIdx.x * 128;

    const int kbase = blockIdx.z * K;
    C += (size_t)blockIdx.z * csplit;

    const int row = tid >> 1;
    const int seg = (tid & 1) << 4;

    const bool bok = (bn + row) < Nact;
    const __half* Ap = A + (size_t)(bm + row) * lda + kbase + seg;
    const __half* Bp = Bw + (size_t)(bn + row) * ldb + kbase + seg;

    uint32_t sbase;
    asm("{ .reg .u64 t; cvta.to.shared.u64 t, %1; cvt.u32.u64 %0, t; }"
        : "=r"(sbase) : "l"(smem));
    const uint32_t dA = sbase + ((uint32_t)row * SPITCH_H + seg) * 2;
    const uint32_t dB = dA + A_HALVES * 2;

    uint32_t aoff[2], boff[4];
#pragma unroll
    for (int mt = 0; mt < 2; mt++)
        aoff[mt] = (((uint32_t)(warp_m * 32 + mt * 16 + (lane & 15))) * SPITCH_H
                    + ((lane >> 4) << 3)) * 2;
#pragma unroll
    for (int nt2 = 0; nt2 < 4; nt2++)
        boff[nt2] = A_HALVES * 2 +
                    (((uint32_t)(warp_n * 64 + nt2 * 16 + (lane & 7) + ((lane >> 4) << 3)))
                     * SPITCH_H + (((lane >> 3) & 1) << 3)) * 2;

    float acc[2][8][4];
#pragma unroll
    for (int mt = 0; mt < 2; mt++)
#pragma unroll
        for (int nt = 0; nt < 8; nt++)
#pragma unroll
            for (int q = 0; q < 4; q++) acc[mt][nt][q] = 0.f;

    const int NC = K >> 5;

    auto issue = [&](int c) {
        const uint32_t so = (uint32_t)(c & (NSTAGE - 1)) * STAGEB;
        const int k0 = c << 5;
        cp16(dA + so,      Ap + k0,     true);
        cp16(dA + so + 16, Ap + k0 + 8, true);
        cp16(dB + so,      Bp + k0,     bok);
        cp16(dB + so + 16, Bp + k0 + 8, bok);
        CP_COMMIT();
    };
    auto compute = [&](int buf) {
        const uint32_t so = sbase + (uint32_t)buf * STAGEB;
#pragma unroll
        for (int ks = 0; ks < 2; ks++) {
            const uint32_t kb = so + ks * 32;
            uint32_t afr[2][4], bfr[4][4];
#pragma unroll
            for (int mt = 0; mt < 2; mt++) ldsm4(afr[mt], kb + aoff[mt]);
#pragma unroll
            for (int nt2 = 0; nt2 < 4; nt2++) ldsm4(bfr[nt2], kb + boff[nt2]);
#pragma unroll
            for (int mt = 0; mt < 2; mt++)
#pragma unroll
                for (int nt2 = 0; nt2 < 4; nt2++) {
                    mma_f16(acc[mt][nt2 * 2],     afr[mt], &bfr[nt2][0]);
                    mma_f16(acc[mt][nt2 * 2 + 1], afr[mt], &bfr[nt2][2]);
                }
        }
    };

    issue(0);
    if (NC > 1) issue(1);

    for (int c = 0; c < NC; c++) {
        if (c + 1 < NC) CP_WAIT(1);
        else            CP_WAIT(0);
        __syncthreads();
        if (c + 2 < NC) issue(c + 2);
        compute(c & (NSTAGE - 1));
    }

#pragma unroll
    for (int mt = 0; mt < 2; mt++) {
        const int r0 = bm + warp_m * 32 + mt * 16 + g;
#pragma unroll
        for (int nt = 0; nt < 8; nt++) {
            const int col = bn + warp_n * 64 + nt * 8 + 2 * t4;
            if (col >= Nact) continue;
#pragma unroll
            for (int hrow = 0; hrow < 2; hrow++) {
                const int r = r0 + hrow * 8;
                float2 v = make_float2(acc[mt][nt][hrow * 2], acc[mt][nt][hrow * 2 + 1]);
                if (EPI == 1) {
                    float2 bs = *(const float2*)(aux + col);
                    v.x += bs.x; v.y += bs.y;
                    v.x = fmaxf(v.x, 0.f) + log1pf(expf(-fabsf(v.x)));
                    v.y = fmaxf(v.y, 0.f) + log1pf(expf(-fabsf(v.y)));
                } else if (EPI == 2) {
                    float2 rv = *(const float2*)(aux + (size_t)r * ldc + col);
                    v.x += rv.x; v.y += rv.y;
                }
                if (sizeof(OutT) == 2) {
                    *(__half2*)((__half*)C + (size_t)r * ldc + col) = __float22half2_rn(v);
                } else {
                    *(float2*)((float*)C + (size_t)r * ldc + col) = v;
                }
            }
        }
    }
}

// ---------------- fp32 -> fp16 conversion ----------------
__global__ __launch_bounds__(256)
void tohalf_kernel(const float* __restrict__ src, __half* __restrict__ dst, int n4)
{
    int i = blockIdx.x * blockDim.x + threadIdx.x;
    if (i >= n4) return;
    float4 v = ((const float4*)src)[i];
    ((__half2*)dst)[i * 2]     = __floats2half2_rn(v.x, v.y);
    ((__half2*)dst)[i * 2 + 1] = __floats2half2_rn(v.z, v.w);
}

// ---------------- split-K reduce -> half xdbl ----------------
__global__ __launch_bounds__(256)
void reduce_split_kernel()
{
    int idx = blockIdx.x * blockDim.x + threadIdx.x;
    if (idx >= BL * XDBL_W) return;
    float s = 0.f;
#pragma unroll
    for (int k = 0; k < SPLITK; k++)
        s += g_part[(size_t)k * BL * XDBL_W + idx];
    g_xdbl_h[idx] = __float2half_rn(s);
}

// ---------------- causal depthwise conv + bias + SiLU (half2, 2 ch/thread) ----------------
__global__ __launch_bounds__(256)
void conv_silu_kernel(const float* __restrict__ cw, const float* __restrict__ cb)
{
    int idx = blockIdx.x * blockDim.x + threadIdx.x;
    if (idx >= BL * D_INNER / 2) return;
    int dp = idx & (D_INNER / 2 - 1);
    int d = dp << 1;
    int row = idx >> 10;
    int l = row & (LSEQ - 1);

    float4 wa = *(const float4*)(cw + d * 4);
    float4 wb = *(const float4*)(cw + d * 4 + 4);
    float2 bias = *(const float2*)(cb + d);
    float a0 = bias.x, a1 = bias.y;

    const __half2* src = (const __half2*)g_xzh + dp;
#pragma unroll
    for (int j = 0; j < 4; j++) {
        int lj = l - 3 + j;
        if (lj >= 0) {
            float2 v = __half22float2(src[(size_t)(row - 3 + j) * 2048]);
            float w0 = (j == 0) ? wa.x : (j == 1) ? wa.y : (j == 2) ? wa.z : wa.w;
            float w1 = (j == 0) ? wb.x : (j == 1) ? wb.y : (j == 2) ? wb.z : wb.w;
            a0 = fmaf(v.x, w0, a0);
            a1 = fmaf(v.y, w1, a1);
        }
    }
    float s0 = a0 / (1.f + __expf(-a0));
    float s1 = a1 / (1.f + __expf(-a1));
    ((__half2*)g_uh)[idx] = __floats2half2_rn(s0, s1);
}

// ---------------- selective scan: 16 lanes/channel, 1 state/lane ----------------
// 4-step groups, level-batched shfl (4 levels), distance-2 group prefetch.
// 4096 channels * 16 lanes = 65536 threads = 256 blocks of 256 (2 channels/warp).
__global__ __launch_bounds__(256)
void scan_kernel(const float* __restrict__ A_log, const float* __restrict__ Dp)
{
    const int tid = threadIdx.x;
    const int ch = blockIdx.x * 16 + (tid >> 4);
    const int b = ch >> 11;
    const int d = ch & (D_INNER - 1);
    const int n = tid & 15;             // state index

    const float An = -expf(A_log[d * D_STATE + n]);
    const float Dd = Dp[d];

    float hn = 0.f;
    const __half* xd = g_xdbl_h + (size_t)b * LSEQ * XDBL_W + DT_RANK + n;
    const size_t base2 = (size_t)b * LSEQ * D_INNER + d;
    const size_t basez = (size_t)b * LSEQ * (2 * D_INNER) + D_INNER + d;

    auto load_group = [&](int l, float* D_, float* U_, float* Z_, float* B_, float* C_) {
#pragma unroll
        for (int j = 0; j < 4; j++) {
            size_t o2 = base2 + (size_t)(l + j) * D_INNER;
            D_[j] = __half2float(g_deltah[o2]);          // broadcast within channel
            U_[j] = __half2float(g_uh[o2]);
        }
        if (n == 0) {
#pragma unroll
            for (int j = 0; j < 4; j++)
                Z_[j] = __half2float(g_xzh[basez + (size_t)(l + j) * (2 * D_INNER)]);
        }
#pragma unroll
        for (int j = 0; j < 4; j++) {
            const __half* xr = xd + (size_t)(l + j) * XDBL_W;
            B_[j] = __half2float(xr[0]);
            C_[j] = __half2float(xr[D_STATE]);
        }
    };

    auto proc = [&](int l0, const float* D_, const float* U_, const float* Z_,
                    const float* B_, const float* C_) {
        float yp[4];
        // Phase A: 4 recurrence steps (1 state per lane).
#pragma unroll
        for (int j = 0; j < 4; j++) {
            float e = __expf(D_[j] * An);
            hn = fmaf(e, hn, D_[j] * U_[j] * B_[j]);
            yp[j] = hn * C_[j];
        }
        // Phase B: level-batched 16-lane reductions.
#pragma unroll
        for (int j = 0; j < 4; j++) yp[j] += __shfl_xor_sync(0xffffffffu, yp[j], 1);
#pragma unroll
        for (int j = 0; j < 4; j++) yp[j] += __shfl_xor_sync(0xffffffffu, yp[j], 2);
#pragma unroll
        for (int j = 0; j < 4; j++) yp[j] += __shfl_xor_sync(0xffffffffu, yp[j], 4);
#pragma unroll
        for (int j = 0; j < 4; j++) yp[j] += __shfl_xor_sync(0xffffffffu, yp[j], 8);
        if (n == 0) {
#pragma unroll
            for (int j = 0; j < 4; j++) {
                float z = Z_[j];
                float sz = z / (1.f + __expf(-z));
                g_yh[base2 + (size_t)(l0 + j) * D_INNER] =
                    __float2half_rn(fmaf(U_[j], Dd, yp[j]) * sz);
            }
        }
    };

    float aD[4], aU[4], aZ[4], aB[4], aC[4];
    float bD[4], bU[4], bZ[4], bB[4], bC[4];
    float tD[4], tU[4], tZ[4], tB[4], tC[4];
    float sD[4], sU[4], sZ[4], sB[4], sC[4];

    load_group(0, aD, aU, aZ, aB, aC);
    load_group(4, bD, bU, bZ, bB, bC);

    for (int l0 = 0; l0 < LSEQ; l0 += 8) {
        const bool more = (l0 + 8) < LSEQ;
        if (more) {
            load_group(l0 + 8,  tD, tU, tZ, tB, tC);
            load_group(l0 + 12, sD, sU, sZ, sB, sC);
        }
        proc(l0,     aD, aU, aZ, aB, aC);
        proc(l0 + 4, bD, bU, bZ, bB, bC);
        if (more) {
#pragma unroll
            for (int j = 0; j < 4; j++) {
                aD[j] = tD[j]; aU[j] = tU[j]; aZ[j] = tZ[j]; aB[j] = tB[j]; aC[j] = tC[j];
                bD[j] = sD[j]; bU[j] = sU[j]; bZ[j] = sZ[j]; bB[j] = sB[j]; bC[j] = sC[j];
            }
        }
    }
}

// ---------------- LayerNorm over last dim (1024) ----------------
__global__ __launch_bounds__(256)
void ln_kernel(const float* __restrict__ lnw, const float* __restrict__ lnb,
               float* __restrict__ out)
{
    int row = blockIdx.x;
    const float* hp = g_h + (size_t)row * D_MODEL;
    int tid = threadIdx.x;

    float v[4];
    float s = 0.f, sq = 0.f;
#pragma unroll
    for (int i = 0; i < 4; i++) {
        v[i] = hp[tid + i * 256];
        s += v[i];
        sq += v[i] * v[i];
    }
#pragma unroll
    for (int off = 16; off; off >>= 1) {
        s += __shfl_xor_sync(0xffffffffu, s, off);
        sq += __shfl_xor_sync(0xffffffffu, sq, off);
    }
    __shared__ float ss[8], ssq[8];
    __shared__ float mu_s, rs_s;
    if ((tid & 31) == 0) { ss[tid >> 5] = s; ssq[tid >> 5] = sq; }
    __syncthreads();
    if (tid == 0) {
        float S = 0.f, SQ = 0.f;
#pragma unroll
        for (int i = 0; i < 8; i++) { S += ss[i]; SQ += ssq[i]; }
        float mu = S * (1.f / D_MODEL);
        float var = SQ * (1.f / D_MODEL) - mu * mu;
        mu_s = mu;
        rs_s = rsqrtf(var + 1e-5f);
    }
    __syncthreads();
    float mu = mu_s, rs = rs_s;
#pragma unroll
    for (int i = 0; i < 4; i++) {
        int c = tid + i * 256;
        out[(size_t)row * D_MODEL + c] = (v[i] - mu) * rs * lnw[c] + lnb[c];
    }
}

// ---------------- host launch ----------------
extern "C" void kernel_launch(void* const* d_in, const int* in_sizes, int n_in,
                              void* d_out, int out_size)
{
    const float* x          = (const float*)d_in[0];
    const float* in_proj_w  = (const float*)d_in[1];
    const float* conv_w     = (const float*)d_in[2];
    const float* conv_b     = (const float*)d_in[3];
    const float* x_proj_w   = (const float*)d_in[4];
    const float* dt_proj_w  = (const float*)d_in[5];
    const float* dt_proj_b  = (const float*)d_in[6];
    const float* A_log      = (const float*)d_in[7];
    const float* Dp         = (const float*)d_in[8];
    const float* out_proj_w = (const float*)d_in[9];
    const float* ln_w       = (const float*)d_in[10];
    const float* ln_b       = (const float*)d_in[11];
    float* out = (float*)d_out;

    float *p_h, *p_part;
    __half *p_xzh, *p_deltah, *p_uh, *p_xdblh, *p_yh, *p_xh;
    __half *p_w1h, *p_w3h, *p_w4h, *p_w6h;
    cudaGetSymbolAddress((void**)&p_h,      g_h);
    cudaGetSymbolAddress((void**)&p_part,   g_part);
    cudaGetSymbolAddress((void**)&p_xzh,    g_xzh);
    cudaGetSymbolAddress((void**)&p_deltah, g_deltah);
    cudaGetSymbolAddress((void**)&p_uh,     g_uh);
    cudaGetSymbolAddress((void**)&p_xdblh,  g_xdbl_h);
    cudaGetSymbolAddress((void**)&p_yh,     g_yh);
    cudaGetSymbolAddress((void**)&p_xh,     g_xh);
    cudaGetSymbolAddress((void**)&p_w1h,    g_w1h);
    cudaGetSymbolAddress((void**)&p_w3h,    g_w3h);
    cudaGetSymbolAddress((void**)&p_w4h,    g_w4h);
    cudaGetSymbolAddress((void**)&p_w6h,    g_w6h);

    const int smemB = NSTAGE * STAGEB;   // 81920
    cudaFuncSetAttribute((const void*)gemm_h<0, __half>, cudaFuncAttributeMaxDynamicSharedMemorySize, smemB);
    cudaFuncSetAttribute((const void*)gemm_h<0, float>,  cudaFuncAttributeMaxDynamicSharedMemorySize, smemB);
    cudaFuncSetAttribute((const void*)gemm_h<1, __half>, cudaFuncAttributeMaxDynamicSharedMemorySize, smemB);
    cudaFuncSetAttribute((const void*)gemm_h<2, float>,  cudaFuncAttributeMaxDynamicSharedMemorySize, smemB);

    auto cvt = [&](const float* s, __half* dvc, int n) {
        tohalf_kernel<<<(n / 4 + 255) / 256, 256>>>(s, dvc, n / 4);
    };
    // launches 0..2 so GEMM1 is the profiled slot (control metric)
    cvt(x,          p_xh,  BL * D_MODEL);
    cvt(in_proj_w,  p_w1h, 2 * D_INNER * D_MODEL);
    cvt(x_proj_w,   p_w3h, XDBL_W * D_INNER);

    // 1) xz = x @ in_proj_w^T   [4096,4096] K=1024  -> half
    gemm_h<0, __half><<<dim3(32, 32), 256, smemB>>>(
        p_xh, D_MODEL, p_w1h, D_MODEL, 2 * D_INNER,
        p_xzh, 2 * D_INNER, nullptr, D_MODEL, 0);

    cvt(dt_proj_w,  p_w4h, D_INNER * DT_RANK);
    cvt(out_proj_w, p_w6h, D_MODEL * D_INNER);

    // 2) u = silu(causal_conv(xi) + cb) -> half
    conv_silu_kernel<<<(BL * D_INNER / 2 + 255) / 256, 256>>>(conv_w, conv_b);
    // 3) x_dbl = u @ x_proj_w^T [4096,96], split-K x8 + reduce -> half
    gemm_h<0, float><<<dim3(1, 32, SPLITK), 256, smemB>>>(
        p_uh, D_INNER, p_w3h, D_INNER, XDBL_W,
        p_part, XDBL_W, nullptr, D_INNER / SPLITK, (size_t)BL * XDBL_W);
    reduce_split_kernel<<<(BL * XDBL_W + 255) / 256, 256>>>();
    // 4) delta = softplus(dt @ dt_proj_w^T + b) [4096,2048] K=64 -> half
    gemm_h<1, __half><<<dim3(16, 32), 256, smemB>>>(
        p_xdblh, XDBL_W, p_w4h, DT_RANK, D_INNER,
        p_deltah, D_INNER, dt_proj_b, DT_RANK, 0);
    // 5) selective scan + skip + gate -> half y (16 lanes/channel)
    scan_kernel<<<256, 256>>>(A_log, Dp);
    // 6) h = y @ out_proj_w^T + x [4096,1024] K=2048 -> float
    gemm_h<2, float><<<dim3(8, 32), 256, smemB>>>(
        p_yh, D_INNER, p_w6h, D_INNER, D_MODEL,
        p_h, D_MODEL, x, D_INNER, 0);
    // 7) LayerNorm -> out
    ln_kernel<<<BL, 256>>>(ln_w, ln_b, out);
}

// round 11
// speedup vs baseline: 1.0465x; 1.0465x over previous
#include <cuda_runtime.h>
#include <cuda_fp16.h>
#include <math.h>
#include <stdint.h>

#define D_MODEL 1024
#define D_INNER 2048
#define D_STATE 16
#define DT_RANK 64
#define NB 2
#define LSEQ 2048
#define BL (NB*LSEQ)            /* 4096 rows total */
#define XDBL_W 96
#define SPLITK 8

// ---------------- scratch (device globals) ----------------
__device__ float  g_h[(size_t)BL * D_MODEL];            // fp32: pre-LN
__device__ float  g_part[(size_t)SPLITK * BL * XDBL_W]; // split-K partials
// fp16 buffers (16B-aligned for cp.async)
__device__ __align__(16) __half g_xzh[(size_t)BL * 2 * D_INNER];
__device__ __align__(16) __half g_deltah[(size_t)BL * D_INNER];
__device__ __align__(16) __half g_uh[(size_t)BL * D_INNER];
__device__ __align__(16) __half g_xdbl_h[(size_t)BL * XDBL_W];
__device__ __align__(16) __half g_yh[(size_t)BL * D_INNER];
__device__ __align__(16) __half g_xh[(size_t)BL * D_MODEL];
__device__ __align__(16) __half g_w1h[(size_t)2 * D_INNER * D_MODEL];
__device__ __align__(16) __half g_w3h[(size_t)XDBL_W * D_INNER];
__device__ __align__(16) __half g_w4h[(size_t)D_INNER * DT_RANK];
__device__ __align__(16) __half g_w6h[(size_t)D_MODEL * D_INNER];

__device__ __forceinline__ void mma_f16(float* d, const uint32_t* a, const uint32_t* b) {
    asm volatile(
        "mma.sync.aligned.m16n8k16.row.col.f32.f16.f16.f32 "
        "{%0,%1,%2,%3}, {%4,%5,%6,%7}, {%8,%9}, {%0,%1,%2,%3};"
        : "+f"(d[0]), "+f"(d[1]), "+f"(d[2]), "+f"(d[3])
        : "r"(a[0]), "r"(a[1]), "r"(a[2]), "r"(a[3]), "r"(b[0]), "r"(b[1]));
}
__device__ __forceinline__ void ldsm4(uint32_t* r, uint32_t addr) {
    asm volatile("ldmatrix.sync.aligned.m8n8.x4.shared.b16 {%0,%1,%2,%3}, [%4];"
                 : "=r"(r[0]), "=r"(r[1]), "=r"(r[2]), "=r"(r[3]) : "r"(addr));
}
__device__ __forceinline__ void cp16(uint32_t dst, const void* src, bool pred) {
    int sz = pred ? 16 : 0;
    asm volatile("cp.async.cg.shared.global [%0], [%1], 16, %2;"
                 :: "r"(dst), "l"(src), "r"(sz) : "memory");
}
#define CP_COMMIT() asm volatile("cp.async.commit_group;" ::: "memory")
#define CP_WAIT(n)  asm volatile("cp.async.wait_group %0;" :: "n"(n) : "memory")

// ================= fp16 mma.sync GEMM, cp.async depth-3 =================
#define SPITCH_H 40
#define A_HALVES (128 * SPITCH_H)
#define STAGE_HALVES (2 * A_HALVES)
#define STAGEB (STAGE_HALVES * 2)
#define NSTAGE 4

template<int EPI, typename OutT>
__global__ __launch_bounds__(256, 2)
void gemm_h(const __half* __restrict__ A, int lda,
            const __half* __restrict__ Bw, int ldb, int Nact,
            OutT* __restrict__ C, int ldc,
            const float* __restrict__ aux, int K, size_t csplit)
{
    extern __shared__ __half smem[];
    const int tid = threadIdx.x;
    const int wid = tid >> 5;
    const int lane = tid & 31;
    const int g = lane >> 2;
    const int t4 = lane & 3;
    const int warp_m = wid >> 1;
    const int warp_n = wid & 1;
    const int bm = blockIdx.y * 128;
    const int bn = blockIdx.x * 128;

    const int kbase = blockIdx.z * K;
    C += (size_t)blockIdx.z * csplit;

    const int row = tid >> 1;
    const int seg = (tid & 1) << 4;

    const bool bok = (bn + row) < Nact;
    const __half* Ap = A + (size_t)(bm + row) * lda + kbase + seg;
    const __half* Bp = Bw + (size_t)(bn + row) * ldb + kbase + seg;

    uint32_t sbase;
    asm("{ .reg .u64 t; cvta.to.shared.u64 t, %1; cvt.u32.u64 %0, t; }"
        : "=r"(sbase) : "l"(smem));
    const uint32_t dA = sbase + ((uint32_t)row * SPITCH_H + seg) * 2;
    const uint32_t dB = dA + A_HALVES * 2;

    uint32_t aoff[2], boff[4];
#pragma unroll
    for (int mt = 0; mt < 2; mt++)
        aoff[mt] = (((uint32_t)(warp_m * 32 + mt * 16 + (lane & 15))) * SPITCH_H
                    + ((lane >> 4) << 3)) * 2;
#pragma unroll
    for (int nt2 = 0; nt2 < 4; nt2++)
        boff[nt2] = A_HALVES * 2 +
                    (((uint32_t)(warp_n * 64 + nt2 * 16 + (lane & 7) + ((lane >> 4) << 3)))
                     * SPITCH_H + (((lane >> 3) & 1) << 3)) * 2;

    float acc[2][8][4];
#pragma unroll
    for (int mt = 0; mt < 2; mt++)
#pragma unroll
        for (int nt = 0; nt < 8; nt++)
#pragma unroll
            for (int q = 0; q < 4; q++) acc[mt][nt][q] = 0.f;

    const int NC = K >> 5;

    auto issue = [&](int c) {
        const uint32_t so = (uint32_t)(c & (NSTAGE - 1)) * STAGEB;
        const int k0 = c << 5;
        cp16(dA + so,      Ap + k0,     true);
        cp16(dA + so + 16, Ap + k0 + 8, true);
        cp16(dB + so,      Bp + k0,     bok);
        cp16(dB + so + 16, Bp + k0 + 8, bok);
        CP_COMMIT();
    };
    auto compute = [&](int buf) {
        const uint32_t so = sbase + (uint32_t)buf * STAGEB;
#pragma unroll
        for (int ks = 0; ks < 2; ks++) {
            const uint32_t kb = so + ks * 32;
            uint32_t afr[2][4], bfr[4][4];
#pragma unroll
            for (int mt = 0; mt < 2; mt++) ldsm4(afr[mt], kb + aoff[mt]);
#pragma unroll
            for (int nt2 = 0; nt2 < 4; nt2++) ldsm4(bfr[nt2], kb + boff[nt2]);
#pragma unroll
            for (int mt = 0; mt < 2; mt++)
#pragma unroll
                for (int nt2 = 0; nt2 < 4; nt2++) {
                    mma_f16(acc[mt][nt2 * 2],     afr[mt], &bfr[nt2][0]);
                    mma_f16(acc[mt][nt2 * 2 + 1], afr[mt], &bfr[nt2][2]);
                }
        }
    };

    // prologue: depth 3
    issue(0);
    if (NC > 1) issue(1);
    if (NC > 2) issue(2);

    for (int c = 0; c < NC; c++) {
        const int rem = NC - c;           // groups still in flight incl. c
        if (rem >= 3)      CP_WAIT(2);
        else if (rem == 2) CP_WAIT(1);
        else               CP_WAIT(0);
        __syncthreads();
        if (c + 3 < NC) issue(c + 3);
        compute(c & (NSTAGE - 1));
    }

#pragma unroll
    for (int mt = 0; mt < 2; mt++) {
        const int r0 = bm + warp_m * 32 + mt * 16 + g;
#pragma unroll
        for (int nt = 0; nt < 8; nt++) {
            const int col = bn + warp_n * 64 + nt * 8 + 2 * t4;
            if (col >= Nact) continue;
#pragma unroll
            for (int hrow = 0; hrow < 2; hrow++) {
                const int r = r0 + hrow * 8;
                float2 v = make_float2(acc[mt][nt][hrow * 2], acc[mt][nt][hrow * 2 + 1]);
                if (EPI == 1) {
                    float2 bs = *(const float2*)(aux + col);
                    v.x += bs.x; v.y += bs.y;
                    v.x = fmaxf(v.x, 0.f) + log1pf(expf(-fabsf(v.x)));
                    v.y = fmaxf(v.y, 0.f) + log1pf(expf(-fabsf(v.y)));
                } else if (EPI == 2) {
                    float2 rv = *(const float2*)(aux + (size_t)r * ldc + col);
                    v.x += rv.x; v.y += rv.y;
                }
                if (sizeof(OutT) == 2) {
                    *(__half2*)((__half*)C + (size_t)r * ldc + col) = __float22half2_rn(v);
                } else {
                    *(float2*)((float*)C + (size_t)r * ldc + col) = v;
                }
            }
        }
    }
}

// ---------------- fp32 -> fp16 conversion ----------------
__global__ __launch_bounds__(256)
void tohalf_kernel(const float* __restrict__ src, __half* __restrict__ dst, int n4)
{
    int i = blockIdx.x * blockDim.x + threadIdx.x;
    if (i >= n4) return;
    float4 v = ((const float4*)src)[i];
    ((__half2*)dst)[i * 2]     = __floats2half2_rn(v.x, v.y);
    ((__half2*)dst)[i * 2 + 1] = __floats2half2_rn(v.z, v.w);
}

// ---------------- split-K reduce -> half xdbl ----------------
__global__ __launch_bounds__(256)
void reduce_split_kernel()
{
    int idx = blockIdx.x * blockDim.x + threadIdx.x;
    if (idx >= BL * XDBL_W) return;
    float s = 0.f;
#pragma unroll
    for (int k = 0; k < SPLITK; k++)
        s += g_part[(size_t)k * BL * XDBL_W + idx];
    g_xdbl_h[idx] = __float2half_rn(s);
}

// ---------------- causal depthwise conv + bias + SiLU (half2, 2 ch/thread) ----------------
__global__ __launch_bounds__(256)
void conv_silu_kernel(const float* __restrict__ cw, const float* __restrict__ cb)
{
    int idx = blockIdx.x * blockDim.x + threadIdx.x;
    if (idx >= BL * D_INNER / 2) return;
    int dp = idx & (D_INNER / 2 - 1);
    int d = dp << 1;
    int row = idx >> 10;
    int l = row & (LSEQ - 1);

    float4 wa = *(const float4*)(cw + d * 4);
    float4 wb = *(const float4*)(cw + d * 4 + 4);
    float2 bias = *(const float2*)(cb + d);
    float a0 = bias.x, a1 = bias.y;

    const __half2* src = (const __half2*)g_xzh + dp;
#pragma unroll
    for (int j = 0; j < 4; j++) {
        int lj = l - 3 + j;
        if (lj >= 0) {
            float2 v = __half22float2(src[(size_t)(row - 3 + j) * 2048]);
            float w0 = (j == 0) ? wa.x : (j == 1) ? wa.y : (j == 2) ? wa.z : wa.w;
            float w1 = (j == 0) ? wb.x : (j == 1) ? wb.y : (j == 2) ? wb.z : wb.w;
            a0 = fmaf(v.x, w0, a0);
            a1 = fmaf(v.y, w1, a1);
        }
    }
    float s0 = a0 / (1.f + __expf(-a0));
    float s1 = a1 / (1.f + __expf(-a1));
    ((__half2*)g_uh)[idx] = __floats2half2_rn(s0, s1);
}

// ---------------- selective scan: 8 lanes/channel, 2 states/lane ----------------
// 8-step fused phases: Phase A = 8 recurrence steps; Phase B = 3 levels x 8 shfl;
// distance-2 group prefetch (8 steps ahead while processing current 8).
__global__ __launch_bounds__(256)
void scan_kernel(const float* __restrict__ A_log, const float* __restrict__ Dp)
{
    const int tid = threadIdx.x;
    const int ch = blockIdx.x * 32 + (tid >> 3);
    const int b = ch >> 11;
    const int d = ch & (D_INNER - 1);
    const int ls = tid & 7;
    const int n0 = ls << 1;

    const float A0 = -expf(A_log[d * D_STATE + n0]);
    const float A1 = -expf(A_log[d * D_STATE + n0 + 1]);
    const float Dd = Dp[d];

    float h0 = 0.f, h1 = 0.f;
    const __half* xd = g_xdbl_h + (size_t)b * LSEQ * XDBL_W + DT_RANK + n0;
    const size_t base2 = (size_t)b * LSEQ * D_INNER + d;
    const size_t basez = (size_t)b * LSEQ * (2 * D_INNER) + D_INNER + d;

    auto load8 = [&](int l, float* D_, float* U_, float* Z_, float2* B_, float2* C_) {
#pragma unroll
        for (int j = 0; j < 8; j++) {
            size_t o2 = base2 + (size_t)(l + j) * D_INNER;
            D_[j] = __half2float(g_deltah[o2]);
            U_[j] = __half2float(g_uh[o2]);
        }
        if (ls == 0) {
#pragma unroll
            for (int j = 0; j < 8; j++)
                Z_[j] = __half2float(g_xzh[basez + (size_t)(l + j) * (2 * D_INNER)]);
        }
#pragma unroll
        for (int j = 0; j < 8; j++) {
            const __half* xr = xd + (size_t)(l + j) * XDBL_W;
            B_[j] = __half22float2(*(const __half2*)(xr));
            C_[j] = __half22float2(*(const __half2*)(xr + D_STATE));
        }
    };

    auto proc8 = [&](int l0, const float* D_, const float* U_, const float* Z_,
                     const float2* B_, const float2* C_) {
        float yp[8];
        // Phase A: 8 recurrence steps, no shuffles.
#pragma unroll
        for (int j = 0; j < 8; j++) {
            float e0 = __expf(D_[j] * A0);
            float e1 = __expf(D_[j] * A1);
            float du = D_[j] * U_[j];
            h0 = fmaf(e0, h0, du * B_[j].x);
            h1 = fmaf(e1, h1, du * B_[j].y);
            yp[j] = fmaf(h0, C_[j].x, h1 * C_[j].y);
        }
        // Phase B: level-batched reductions, 8 independent chains per level.
#pragma unroll
        for (int j = 0; j < 8; j++) yp[j] += __shfl_xor_sync(0xffffffffu, yp[j], 1);
#pragma unroll
        for (int j = 0; j < 8; j++) yp[j] += __shfl_xor_sync(0xffffffffu, yp[j], 2);
#pragma unroll
        for (int j = 0; j < 8; j++) yp[j] += __shfl_xor_sync(0xffffffffu, yp[j], 4);
        if (ls == 0) {
#pragma unroll
            for (int j = 0; j < 8; j++) {
                float z = Z_[j];
                float sz = z / (1.f + __expf(-z));
                g_yh[base2 + (size_t)(l0 + j) * D_INNER] =
                    __float2half_rn(fmaf(U_[j], Dd, yp[j]) * sz);
            }
        }
    };

    float aD[8], aU[8], aZ[8]; float2 aB[8], aC[8];
    float tD[8], tU[8], tZ[8]; float2 tB[8], tC[8];

    load8(0, aD, aU, aZ, aB, aC);

    for (int l0 = 0; l0 < LSEQ; l0 += 8) {
        const bool more = (l0 + 8) < LSEQ;
        if (more) load8(l0 + 8, tD, tU, tZ, tB, tC);
        proc8(l0, aD, aU, aZ, aB, aC);
        if (more) {
#pragma unroll
            for (int j = 0; j < 8; j++) {
                aD[j] = tD[j]; aU[j] = tU[j]; aZ[j] = tZ[j];
                aB[j] = tB[j]; aC[j] = tC[j];
            }
        }
    }
}

// ---------------- LayerNorm over last dim (1024) ----------------
__global__ __launch_bounds__(256)
void ln_kernel(const float* __restrict__ lnw, const float* __restrict__ lnb,
               float* __restrict__ out)
{
    int row = blockIdx.x;
    const float* hp = g_h + (size_t)row * D_MODEL;
    int tid = threadIdx.x;

    float v[4];
    float s = 0.f, sq = 0.f;
#pragma unroll
    for (int i = 0; i < 4; i++) {
        v[i] = hp[tid + i * 256];
        s += v[i];
        sq += v[i] * v[i];
    }
#pragma unroll
    for (int off = 16; off; off >>= 1) {
        s += __shfl_xor_sync(0xffffffffu, s, off);
        sq += __shfl_xor_sync(0xffffffffu, sq, off);
    }
    __shared__ float ss[8], ssq[8];
    __shared__ float mu_s, rs_s;
    if ((tid & 31) == 0) { ss[tid >> 5] = s; ssq[tid >> 5] = sq; }
    __syncthreads();
    if (tid == 0) {
        float S = 0.f, SQ = 0.f;
#pragma unroll
        for (int i = 0; i < 8; i++) { S += ss[i]; SQ += ssq[i]; }
        float mu = S * (1.f / D_MODEL);
        float var = SQ * (1.f / D_MODEL) - mu * mu;
        mu_s = mu;
        rs_s = rsqrtf(var + 1e-5f);
    }
    __syncthreads();
    float mu = mu_s, rs = rs_s;
#pragma unroll
    for (int i = 0; i < 4; i++) {
        int c = tid + i * 256;
        out[(size_t)row * D_MODEL + c] = (v[i] - mu) * rs * lnw[c] + lnb[c];
    }
}

// ---------------- host launch ----------------
extern "C" void kernel_launch(void* const* d_in, const int* in_sizes, int n_in,
                              void* d_out, int out_size)
{
    const float* x          = (const float*)d_in[0];
    const float* in_proj_w  = (const float*)d_in[1];
    const float* conv_w     = (const float*)d_in[2];
    const float* conv_b     = (const float*)d_in[3];
    const float* x_proj_w   = (const float*)d_in[4];
    const float* dt_proj_w  = (const float*)d_in[5];
    const float* dt_proj_b  = (const float*)d_in[6];
    const float* A_log      = (const float*)d_in[7];
    const float* Dp         = (const float*)d_in[8];
    const float* out_proj_w = (const float*)d_in[9];
    const float* ln_w       = (const float*)d_in[10];
    const float* ln_b       = (const float*)d_in[11];
    float* out = (float*)d_out;

    float *p_h, *p_part;
    __half *p_xzh, *p_deltah, *p_uh, *p_xdblh, *p_yh, *p_xh;
    __half *p_w1h, *p_w3h, *p_w4h, *p_w6h;
    cudaGetSymbolAddress((void**)&p_h,      g_h);
    cudaGetSymbolAddress((void**)&p_part,   g_part);
    cudaGetSymbolAddress((void**)&p_xzh,    g_xzh);
    cudaGetSymbolAddress((void**)&p_deltah, g_deltah);
    cudaGetSymbolAddress((void**)&p_uh,     g_uh);
    cudaGetSymbolAddress((void**)&p_xdblh,  g_xdbl_h);
    cudaGetSymbolAddress((void**)&p_yh,     g_yh);
    cudaGetSymbolAddress((void**)&p_xh,     g_xh);
    cudaGetSymbolAddress((void**)&p_w1h,    g_w1h);
    cudaGetSymbolAddress((void**)&p_w3h,    g_w3h);
    cudaGetSymbolAddress((void**)&p_w4h,    g_w4h);
    cudaGetSymbolAddress((void**)&p_w6h,    g_w6h);

    const int smemB = NSTAGE * STAGEB;   // 81920
    cudaFuncSetAttribute((const void*)gemm_h<0, __half>, cudaFuncAttributeMaxDynamicSharedMemorySize, smemB);
    cudaFuncSetAttribute((const void*)gemm_h<0, float>,  cudaFuncAttributeMaxDynamicSharedMemorySize, smemB);
    cudaFuncSetAttribute((const void*)gemm_h<1, __half>, cudaFuncAttributeMaxDynamicSharedMemorySize, smemB);
    cudaFuncSetAttribute((const void*)gemm_h<2, float>,  cudaFuncAttributeMaxDynamicSharedMemorySize, smemB);

    auto cvt = [&](const float* s, __half* dvc, int n) {
        tohalf_kernel<<<(n / 4 + 255) / 256, 256>>>(s, dvc, n / 4);
    };
    // launches 0..2 so GEMM1 is the profiled slot (control metric)
    cvt(x,          p_xh,  BL * D_MODEL);
    cvt(in_proj_w,  p_w1h, 2 * D_INNER * D_MODEL);
    cvt(x_proj_w,   p_w3h, XDBL_W * D_INNER);

    // 1) xz = x @ in_proj_w^T   [4096,4096] K=1024  -> half
    gemm_h<0, __half><<<dim3(32, 32), 256, smemB>>>(
        p_xh, D_MODEL, p_w1h, D_MODEL, 2 * D_INNER,
        p_xzh, 2 * D_INNER, nullptr, D_MODEL, 0);

    cvt(dt_proj_w,  p_w4h, D_INNER * DT_RANK);
    cvt(out_proj_w, p_w6h, D_MODEL * D_INNER);

    // 2) u = silu(causal_conv(xi) + cb) -> half
    conv_silu_kernel<<<(BL * D_INNER / 2 + 255) / 256, 256>>>(conv_w, conv_b);
    // 3) x_dbl = u @ x_proj_w^T [4096,96], split-K x8 + reduce -> half
    gemm_h<0, float><<<dim3(1, 32, SPLITK), 256, smemB>>>(
        p_uh, D_INNER, p_w3h, D_INNER, XDBL_W,
        p_part, XDBL_W, nullptr, D_INNER / SPLITK, (size_t)BL * XDBL_W);
    reduce_split_kernel<<<(BL * XDBL_W + 255) / 256, 256>>>();
    // 4) delta = softplus(dt @ dt_proj_w^T + b) [4096,2048] K=64 -> half
    gemm_h<1, __half><<<dim3(16, 32), 256, smemB>>>(
        p_xdblh, XDBL_W, p_w4h, DT_RANK, D_INNER,
        p_deltah, D_INNER, dt_proj_b, DT_RANK, 0);
    // 5) selective scan + skip + gate -> half y (8 lanes/ch, fused 8-step groups)
    scan_kernel<<<128, 256>>>(A_log, Dp);
    // 6) h = y @ out_proj_w^T + x [4096,1024] K=2048 -> float
    gemm_h<2, float><<<dim3(8, 32), 256, smemB>>>(
        p_yh, D_INNER, p_w6h, D_INNER, D_MODEL,
        p_h, D_MODEL, x, D_INNER, 0);
    // 7) LayerNorm -> out
    ln_kernel<<<BL, 256>>>(ln_w, ln_b, out);
}

// round 12
// speedup vs baseline: 1.0598x; 1.0126x over previous
#include <cuda_runtime.h>
#include <cuda_fp16.h>
#include <math.h>
#include <stdint.h>

#define D_MODEL 1024
#define D_INNER 2048
#define D_STATE 16
#define DT_RANK 64
#define NB 2
#define LSEQ 2048
#define BL (NB*LSEQ)            /* 4096 rows total */
#define XDBL_W 96
#define SPLITK 8

// ---------------- scratch (device globals) ----------------
__device__ float  g_h[(size_t)BL * D_MODEL];            // fp32: pre-LN
__device__ float  g_part[(size_t)SPLITK * BL * XDBL_W]; // split-K partials
// fp16 buffers (16B-aligned for cp.async)
__device__ __align__(16) __half g_xzh[(size_t)BL * 2 * D_INNER];  // xi | silu(z)
__device__ __align__(16) __half g_deltah[(size_t)BL * D_INNER];
__device__ __align__(16) __half g_uh[(size_t)BL * D_INNER];
__device__ __align__(16) __half g_xdbl_h[(size_t)BL * XDBL_W];
__device__ __align__(16) __half g_yh[(size_t)BL * D_INNER];
__device__ __align__(16) __half g_xh[(size_t)BL * D_MODEL];
__device__ __align__(16) __half g_w1h[(size_t)2 * D_INNER * D_MODEL];
__device__ __align__(16) __half g_w3h[(size_t)XDBL_W * D_INNER];
__device__ __align__(16) __half g_w4h[(size_t)D_INNER * DT_RANK];
__device__ __align__(16) __half g_w6h[(size_t)D_MODEL * D_INNER];

__device__ __forceinline__ void mma_f16(float* d, const uint32_t* a, const uint32_t* b) {
    asm volatile(
        "mma.sync.aligned.m16n8k16.row.col.f32.f16.f16.f32 "
        "{%0,%1,%2,%3}, {%4,%5,%6,%7}, {%8,%9}, {%0,%1,%2,%3};"
        : "+f"(d[0]), "+f"(d[1]), "+f"(d[2]), "+f"(d[3])
        : "r"(a[0]), "r"(a[1]), "r"(a[2]), "r"(a[3]), "r"(b[0]), "r"(b[1]));
}
__device__ __forceinline__ void ldsm4(uint32_t* r, uint32_t addr) {
    asm volatile("ldmatrix.sync.aligned.m8n8.x4.shared.b16 {%0,%1,%2,%3}, [%4];"
                 : "=r"(r[0]), "=r"(r[1]), "=r"(r[2]), "=r"(r[3]) : "r"(addr));
}
__device__ __forceinline__ void cp16(uint32_t dst, const void* src, bool pred) {
    int sz = pred ? 16 : 0;
    asm volatile("cp.async.cg.shared.global [%0], [%1], 16, %2;"
                 :: "r"(dst), "l"(src), "r"(sz) : "memory");
}
#define CP_COMMIT() asm volatile("cp.async.commit_group;" ::: "memory")
#define CP_WAIT(n)  asm volatile("cp.async.wait_group %0;" :: "n"(n) : "memory")

// ================= fp16 mma.sync GEMM, cp.async depth-3 =================
// EPI: 0 plain, 1 softplus(acc+aux[col]), 2 acc+aux[row*ldc+col],
//      3 silu on cols >= ldc/2 (GEMM1: z-gate pre-activation)
#define SPITCH_H 40
#define A_HALVES (128 * SPITCH_H)
#define STAGE_HALVES (2 * A_HALVES)
#define STAGEB (STAGE_HALVES * 2)
#define NSTAGE 4

template<int EPI, typename OutT>
__global__ __launch_bounds__(256, 2)
void gemm_h(const __half* __restrict__ A, int lda,
            const __half* __restrict__ Bw, int ldb, int Nact,
            OutT* __restrict__ C, int ldc,
            const float* __restrict__ aux, int K, size_t csplit)
{
    extern __shared__ __half smem[];
    const int tid = threadIdx.x;
    const int wid = tid >> 5;
    const int lane = tid & 31;
    const int g = lane >> 2;
    const int t4 = lane & 3;
    const int warp_m = wid >> 1;
    const int warp_n = wid & 1;
    const int bm = blockIdx.y * 128;
    const int bn = blockIdx.x * 128;

    const int kbase = blockIdx.z * K;
    C += (size_t)blockIdx.z * csplit;

    const int row = tid >> 1;
    const int seg = (tid & 1) << 4;

    const bool bok = (bn + row) < Nact;
    const __half* Ap = A + (size_t)(bm + row) * lda + kbase + seg;
    const __half* Bp = Bw + (size_t)(bn + row) * ldb + kbase + seg;

    uint32_t sbase;
    asm("{ .reg .u64 t; cvta.to.shared.u64 t, %1; cvt.u32.u64 %0, t; }"
        : "=r"(sbase) : "l"(smem));
    const uint32_t dA = sbase + ((uint32_t)row * SPITCH_H + seg) * 2;
    const uint32_t dB = dA + A_HALVES * 2;

    uint32_t aoff[2], boff[4];
#pragma unroll
    for (int mt = 0; mt < 2; mt++)
        aoff[mt] = (((uint32_t)(warp_m * 32 + mt * 16 + (lane & 15))) * SPITCH_H
                    + ((lane >> 4) << 3)) * 2;
#pragma unroll
    for (int nt2 = 0; nt2 < 4; nt2++)
        boff[nt2] = A_HALVES * 2 +
                    (((uint32_t)(warp_n * 64 + nt2 * 16 + (lane & 7) + ((lane >> 4) << 3)))
                     * SPITCH_H + (((lane >> 3) & 1) << 3)) * 2;

    float acc[2][8][4];
#pragma unroll
    for (int mt = 0; mt < 2; mt++)
#pragma unroll
        for (int nt = 0; nt < 8; nt++)
#pragma unroll
            for (int q = 0; q < 4; q++) acc[mt][nt][q] = 0.f;

    const int NC = K >> 5;

    auto issue = [&](int c) {
        const uint32_t so = (uint32_t)(c & (NSTAGE - 1)) * STAGEB;
        const int k0 = c << 5;
        cp16(dA + so,      Ap + k0,     true);
        cp16(dA + so + 16, Ap + k0 + 8, true);
        cp16(dB + so,      Bp + k0,     bok);
        cp16(dB + so + 16, Bp + k0 + 8, bok);
        CP_COMMIT();
    };
    auto compute = [&](int buf) {
        const uint32_t so = sbase + (uint32_t)buf * STAGEB;
#pragma unroll
        for (int ks = 0; ks < 2; ks++) {
            const uint32_t kb = so + ks * 32;
            uint32_t afr[2][4], bfr[4][4];
#pragma unroll
            for (int mt = 0; mt < 2; mt++) ldsm4(afr[mt], kb + aoff[mt]);
#pragma unroll
            for (int nt2 = 0; nt2 < 4; nt2++) ldsm4(bfr[nt2], kb + boff[nt2]);
#pragma unroll
            for (int mt = 0; mt < 2; mt++)
#pragma unroll
                for (int nt2 = 0; nt2 < 4; nt2++) {
                    mma_f16(acc[mt][nt2 * 2],     afr[mt], &bfr[nt2][0]);
                    mma_f16(acc[mt][nt2 * 2 + 1], afr[mt], &bfr[nt2][2]);
                }
        }
    };

    // prologue: depth 3
    issue(0);
    if (NC > 1) issue(1);
    if (NC > 2) issue(2);

    for (int c = 0; c < NC; c++) {
        const int rem = NC - c;
        if (rem >= 3)      CP_WAIT(2);
        else if (rem == 2) CP_WAIT(1);
        else               CP_WAIT(0);
        __syncthreads();
        if (c + 3 < NC) issue(c + 3);
        compute(c & (NSTAGE - 1));
    }

#pragma unroll
    for (int mt = 0; mt < 2; mt++) {
        const int r0 = bm + warp_m * 32 + mt * 16 + g;
#pragma unroll
        for (int nt = 0; nt < 8; nt++) {
            const int col = bn + warp_n * 64 + nt * 8 + 2 * t4;
            if (col >= Nact) continue;
#pragma unroll
            for (int hrow = 0; hrow < 2; hrow++) {
                const int r = r0 + hrow * 8;
                float2 v = make_float2(acc[mt][nt][hrow * 2], acc[mt][nt][hrow * 2 + 1]);
                if (EPI == 1) {
                    float2 bs = *(const float2*)(aux + col);
                    v.x += bs.x; v.y += bs.y;
                    v.x = fmaxf(v.x, 0.f) + log1pf(expf(-fabsf(v.x)));
                    v.y = fmaxf(v.y, 0.f) + log1pf(expf(-fabsf(v.y)));
                } else if (EPI == 2) {
                    float2 rv = *(const float2*)(aux + (size_t)r * ldc + col);
                    v.x += rv.x; v.y += rv.y;
                } else if (EPI == 3) {
                    if (col >= (ldc >> 1)) {       // z half: pre-apply silu gate
                        v.x = v.x / (1.f + __expf(-v.x));
                        v.y = v.y / (1.f + __expf(-v.y));
                    }
                }
                if (sizeof(OutT) == 2) {
                    *(__half2*)((__half*)C + (size_t)r * ldc + col) = __float22half2_rn(v);
                } else {
                    *(float2*)((float*)C + (size_t)r * ldc + col) = v;
                }
            }
        }
    }
}

// ---------------- fp32 -> fp16 conversion ----------------
__global__ __launch_bounds__(256)
void tohalf_kernel(const float* __restrict__ src, __half* __restrict__ dst, int n4)
{
    int i = blockIdx.x * blockDim.x + threadIdx.x;
    if (i >= n4) return;
    float4 v = ((const float4*)src)[i];
    ((__half2*)dst)[i * 2]     = __floats2half2_rn(v.x, v.y);
    ((__half2*)dst)[i * 2 + 1] = __floats2half2_rn(v.z, v.w);
}

// ---------------- split-K reduce -> half xdbl ----------------
__global__ __launch_bounds__(256)
void reduce_split_kernel()
{
    int idx = blockIdx.x * blockDim.x + threadIdx.x;
    if (idx >= BL * XDBL_W) return;
    float s = 0.f;
#pragma unroll
    for (int k = 0; k < SPLITK; k++)
        s += g_part[(size_t)k * BL * XDBL_W + idx];
    g_xdbl_h[idx] = __float2half_rn(s);
}

// ---------------- causal depthwise conv + bias + SiLU (half2, 2 ch/thread) ----------------
__global__ __launch_bounds__(256)
void conv_silu_kernel(const float* __restrict__ cw, const float* __restrict__ cb)
{
    int idx = blockIdx.x * blockDim.x + threadIdx.x;
    if (idx >= BL * D_INNER / 2) return;
    int dp = idx & (D_INNER / 2 - 1);
    int d = dp << 1;
    int row = idx >> 10;
    int l = row & (LSEQ - 1);

    float4 wa = *(const float4*)(cw + d * 4);
    float4 wb = *(const float4*)(cw + d * 4 + 4);
    float2 bias = *(const float2*)(cb + d);
    float a0 = bias.x, a1 = bias.y;

    const __half2* src = (const __half2*)g_xzh + dp;
#pragma unroll
    for (int j = 0; j < 4; j++) {
        int lj = l - 3 + j;
        if (lj >= 0) {
            float2 v = __half22float2(src[(size_t)(row - 3 + j) * 2048]);
            float w0 = (j == 0) ? wa.x : (j == 1) ? wa.y : (j == 2) ? wa.z : wa.w;
            float w1 = (j == 0) ? wb.x : (j == 1) ? wb.y : (j == 2) ? wb.z : wb.w;
            a0 = fmaf(v.x, w0, a0);
            a1 = fmaf(v.y, w1, a1);
        }
    }
    float s0 = a0 / (1.f + __expf(-a0));
    float s1 = a1 / (1.f + __expf(-a1));
    ((__half2*)g_uh)[idx] = __floats2half2_rn(s0, s1);
}

// ---------------- selective scan: 8 lanes/channel, 2 states/lane (R9 shape) ----------------
// 4-step groups, level-batched shfl, distance-2 group prefetch; z-gate PRE-ACTIVATED.
__global__ __launch_bounds__(256)
void scan_kernel(const float* __restrict__ A_log, const float* __restrict__ Dp)
{
    const int tid = threadIdx.x;
    const int ch = blockIdx.x * 32 + (tid >> 3);
    const int b = ch >> 11;
    const int d = ch & (D_INNER - 1);
    const int ls = tid & 7;
    const int n0 = ls << 1;

    const float A0 = -expf(A_log[d * D_STATE + n0]);
    const float A1 = -expf(A_log[d * D_STATE + n0 + 1]);
    const float Dd = Dp[d];

    float h0 = 0.f, h1 = 0.f;
    const __half* xd = g_xdbl_h + (size_t)b * LSEQ * XDBL_W + DT_RANK + n0;
    const size_t base2 = (size_t)b * LSEQ * D_INNER + d;
    const size_t basez = (size_t)b * LSEQ * (2 * D_INNER) + D_INNER + d;

    auto load_group = [&](int l, float* D_, float* U_, float* Z_, float2* B_, float2* C_) {
#pragma unroll
        for (int j = 0; j < 4; j++) {
            size_t o2 = base2 + (size_t)(l + j) * D_INNER;
            D_[j] = __half2float(g_deltah[o2]);
            U_[j] = __half2float(g_uh[o2]);
        }
        if (ls == 0) {
#pragma unroll
            for (int j = 0; j < 4; j++)
                Z_[j] = __half2float(g_xzh[basez + (size_t)(l + j) * (2 * D_INNER)]);
        }
#pragma unroll
        for (int j = 0; j < 4; j++) {
            const __half* xr = xd + (size_t)(l + j) * XDBL_W;
            B_[j] = __half22float2(*(const __half2*)(xr));
            C_[j] = __half22float2(*(const __half2*)(xr + D_STATE));
        }
    };

    auto proc = [&](int l0, const float* D_, const float* U_, const float* Z_,
                    const float2* B_, const float2* C_) {
        float yp[4];
#pragma unroll
        for (int j = 0; j < 4; j++) {
            float e0 = __expf(D_[j] * A0);
            float e1 = __expf(D_[j] * A1);
            float du = D_[j] * U_[j];
            h0 = fmaf(e0, h0, du * B_[j].x);
            h1 = fmaf(e1, h1, du * B_[j].y);
            yp[j] = fmaf(h0, C_[j].x, h1 * C_[j].y);
        }
#pragma unroll
        for (int j = 0; j < 4; j++) yp[j] += __shfl_xor_sync(0xffffffffu, yp[j], 1);
#pragma unroll
        for (int j = 0; j < 4; j++) yp[j] += __shfl_xor_sync(0xffffffffu, yp[j], 2);
#pragma unroll
        for (int j = 0; j < 4; j++) yp[j] += __shfl_xor_sync(0xffffffffu, yp[j], 4);
        if (ls == 0) {
#pragma unroll
            for (int j = 0; j < 4; j++) {
                // Z_ already holds silu(z) (folded into GEMM1 epilogue)
                g_yh[base2 + (size_t)(l0 + j) * D_INNER] =
                    __float2half_rn(fmaf(U_[j], Dd, yp[j]) * Z_[j]);
            }
        }
    };

    float aD[4], aU[4], aZ[4]; float2 aB[4], aC[4];
    float bD[4], bU[4], bZ[4]; float2 bB[4], bC[4];
    float tD[4], tU[4], tZ[4]; float2 tB[4], tC[4];
    float sD[4], sU[4], sZ[4]; float2 sB[4], sC[4];

    load_group(0, aD, aU, aZ, aB, aC);
    load_group(4, bD, bU, bZ, bB, bC);

    for (int l0 = 0; l0 < LSEQ; l0 += 8) {
        const bool more = (l0 + 8) < LSEQ;
        if (more) {
            load_group(l0 + 8,  tD, tU, tZ, tB, tC);
            load_group(l0 + 12, sD, sU, sZ, sB, sC);
        }
        proc(l0,     aD, aU, aZ, aB, aC);
        proc(l0 + 4, bD, bU, bZ, bB, bC);
        if (more) {
#pragma unroll
            for (int j = 0; j < 4; j++) {
                aD[j] = tD[j]; aU[j] = tU[j]; aZ[j] = tZ[j]; aB[j] = tB[j]; aC[j] = tC[j];
                bD[j] = sD[j]; bU[j] = sU[j]; bZ[j] = sZ[j]; bB[j] = sB[j]; bC[j] = sC[j];
            }
        }
    }
}

// ---------------- LayerNorm over last dim (1024) ----------------
__global__ __launch_bounds__(256)
void ln_kernel(const float* __restrict__ lnw, const float* __restrict__ lnb,
               float* __restrict__ out)
{
    int row = blockIdx.x;
    const float* hp = g_h + (size_t)row * D_MODEL;
    int tid = threadIdx.x;

    float v[4];
    float s = 0.f, sq = 0.f;
#pragma unroll
    for (int i = 0; i < 4; i++) {
        v[i] = hp[tid + i * 256];
        s += v[i];
        sq += v[i] * v[i];
    }
#pragma unroll
    for (int off = 16; off; off >>= 1) {
        s += __shfl_xor_sync(0xffffffffu, s, off);
        sq += __shfl_xor_sync(0xffffffffu, sq, off);
    }
    __shared__ float ss[8], ssq[8];
    __shared__ float mu_s, rs_s;
    if ((tid & 31) == 0) { ss[tid >> 5] = s; ssq[tid >> 5] = sq; }
    __syncthreads();
    if (tid == 0) {
        float S = 0.f, SQ = 0.f;
#pragma unroll
        for (int i = 0; i < 8; i++) { S += ss[i]; SQ += ssq[i]; }
        float mu = S * (1.f / D_MODEL);
        float var = SQ * (1.f / D_MODEL) - mu * mu;
        mu_s = mu;
        rs_s = rsqrtf(var + 1e-5f);
    }
    __syncthreads();
    float mu = mu_s, rs = rs_s;
#pragma unroll
    for (int i = 0; i < 4; i++) {
        int c = tid + i * 256;
        out[(size_t)row * D_MODEL + c] = (v[i] - mu) * rs * lnw[c] + lnb[c];
    }
}

// ---------------- host launch ----------------
extern "C" void kernel_launch(void* const* d_in, const int* in_sizes, int n_in,
                              void* d_out, int out_size)
{
    const float* x          = (const float*)d_in[0];
    const float* in_proj_w  = (const float*)d_in[1];
    const float* conv_w     = (const float*)d_in[2];
    const float* conv_b     = (const float*)d_in[3];
    const float* x_proj_w   = (const float*)d_in[4];
    const float* dt_proj_w  = (const float*)d_in[5];
    const float* dt_proj_b  = (const float*)d_in[6];
    const float* A_log      = (const float*)d_in[7];
    const float* Dp         = (const float*)d_in[8];
    const float* out_proj_w = (const float*)d_in[9];
    const float* ln_w       = (const float*)d_in[10];
    const float* ln_b       = (const float*)d_in[11];
    float* out = (float*)d_out;

    float *p_h, *p_part;
    __half *p_xzh, *p_deltah, *p_uh, *p_xdblh, *p_yh, *p_xh;
    __half *p_w1h, *p_w3h, *p_w4h, *p_w6h;
    cudaGetSymbolAddress((void**)&p_h,      g_h);
    cudaGetSymbolAddress((void**)&p_part,   g_part);
    cudaGetSymbolAddress((void**)&p_xzh,    g_xzh);
    cudaGetSymbolAddress((void**)&p_deltah, g_deltah);
    cudaGetSymbolAddress((void**)&p_uh,     g_uh);
    cudaGetSymbolAddress((void**)&p_xdblh,  g_xdbl_h);
    cudaGetSymbolAddress((void**)&p_yh,     g_yh);
    cudaGetSymbolAddress((void**)&p_xh,     g_xh);
    cudaGetSymbolAddress((void**)&p_w1h,    g_w1h);
    cudaGetSymbolAddress((void**)&p_w3h,    g_w3h);
    cudaGetSymbolAddress((void**)&p_w4h,    g_w4h);
    cudaGetSymbolAddress((void**)&p_w6h,    g_w6h);

    const int smemB = NSTAGE * STAGEB;   // 81920
    cudaFuncSetAttribute((const void*)gemm_h<3, __half>, cudaFuncAttributeMaxDynamicSharedMemorySize, smemB);
    cudaFuncSetAttribute((const void*)gemm_h<0, float>,  cudaFuncAttributeMaxDynamicSharedMemorySize, smemB);
    cudaFuncSetAttribute((const void*)gemm_h<1, __half>, cudaFuncAttributeMaxDynamicSharedMemorySize, smemB);
    cudaFuncSetAttribute((const void*)gemm_h<2, float>,  cudaFuncAttributeMaxDynamicSharedMemorySize, smemB);

    auto cvt = [&](const float* s, __half* dvc, int n) {
        tohalf_kernel<<<(n / 4 + 255) / 256, 256>>>(s, dvc, n / 4);
    };
    // launches 0..2 so GEMM1 is the profiled slot (control metric)
    cvt(x,          p_xh,  BL * D_MODEL);
    cvt(in_proj_w,  p_w1h, 2 * D_INNER * D_MODEL);
    cvt(x_proj_w,   p_w3h, XDBL_W * D_INNER);

    // 1) xz = x @ in_proj_w^T [4096,4096] K=1024 -> half; silu on z half (EPI=3)
    gemm_h<3, __half><<<dim3(32, 32), 256, smemB>>>(
        p_xh, D_MODEL, p_w1h, D_MODEL, 2 * D_INNER,
        p_xzh, 2 * D_INNER, nullptr, D_MODEL, 0);

    cvt(dt_proj_w,  p_w4h, D_INNER * DT_RANK);
    cvt(out_proj_w, p_w6h, D_MODEL * D_INNER);

    // 2) u = silu(causal_conv(xi) + cb) -> half
    conv_silu_kernel<<<(BL * D_INNER / 2 + 255) / 256, 256>>>(conv_w, conv_b);
    // 3) x_dbl = u @ x_proj_w^T [4096,96], split-K x8 + reduce -> half
    gemm_h<0, float><<<dim3(1, 32, SPLITK), 256, smemB>>>(
        p_uh, D_INNER, p_w3h, D_INNER, XDBL_W,
        p_part, XDBL_W, nullptr, D_INNER / SPLITK, (size_t)BL * XDBL_W);
    reduce_split_kernel<<<(BL * XDBL_W + 255) / 256, 256>>>();
    // 4) delta = softplus(dt @ dt_proj_w^T + b) [4096,2048] K=64 -> half
    gemm_h<1, __half><<<dim3(16, 32), 256, smemB>>>(
        p_xdblh, XDBL_W, p_w4h, DT_RANK, D_INNER,
        p_deltah, D_INNER, dt_proj_b, DT_RANK, 0);
    // 5) selective scan + skip + gate (pre-activated z) -> half y
    scan_kernel<<<128, 256>>>(A_log, Dp);
    // 6) h = y @ out_proj_w^T + x [4096,1024] K=2048 -> float
    gemm_h<2, float><<<dim3(8, 32), 256, smemB>>>(
        p_yh, D_INNER, p_w6h, D_INNER, D_MODEL,
        p_h, D_MODEL, x, D_INNER, 0);
    // 7) LayerNorm -> out
    ln_kernel<<<BL, 256>>>(ln_w, ln_b, out);
}

// round 13
// speedup vs baseline: 1.1199x; 1.0568x over previous
#include <cuda_runtime.h>
#include <cuda_fp16.h>
#include <math.h>
#include <stdint.h>

#define D_MODEL 1024
#define D_INNER 2048
#define D_STATE 16
#define DT_RANK 64
#define NB 2
#define LSEQ 2048
#define BL (NB*LSEQ)            /* 4096 rows total */
#define XDBL_W 96
#define SPLITK 8

// ---------------- scratch (device globals) ----------------
__device__ float  g_h[(size_t)BL * D_MODEL];            // fp32: pre-LN
__device__ float  g_part[(size_t)SPLITK * BL * XDBL_W]; // split-K partials
// fp16 buffers (16B-aligned for cp.async)
__device__ __align__(16) __half g_xzh[(size_t)BL * 2 * D_INNER];
__device__ __align__(16) __half g_deltah[(size_t)BL * D_INNER];
__device__ __align__(16) __half g_uh[(size_t)BL * D_INNER];
__device__ __align__(16) __half g_xdbl_h[(size_t)BL * XDBL_W];
__device__ __align__(16) __half g_yh[(size_t)BL * D_INNER];
__device__ __align__(16) __half g_xh[(size_t)BL * D_MODEL];
__device__ __align__(16) __half g_w1h[(size_t)2 * D_INNER * D_MODEL];
__device__ __align__(16) __half g_w3h[(size_t)XDBL_W * D_INNER];
__device__ __align__(16) __half g_w4h[(size_t)D_INNER * DT_RANK];
__device__ __align__(16) __half g_w6h[(size_t)D_MODEL * D_INNER];

__device__ __forceinline__ void mma_f16(float* d, const uint32_t* a, const uint32_t* b) {
    asm volatile(
        "mma.sync.aligned.m16n8k16.row.col.f32.f16.f16.f32 "
        "{%0,%1,%2,%3}, {%4,%5,%6,%7}, {%8,%9}, {%0,%1,%2,%3};"
        : "+f"(d[0]), "+f"(d[1]), "+f"(d[2]), "+f"(d[3])
        : "r"(a[0]), "r"(a[1]), "r"(a[2]), "r"(a[3]), "r"(b[0]), "r"(b[1]));
}
__device__ __forceinline__ void ldsm4(uint32_t* r, uint32_t addr) {
    asm volatile("ldmatrix.sync.aligned.m8n8.x4.shared.b16 {%0,%1,%2,%3}, [%4];"
                 : "=r"(r[0]), "=r"(r[1]), "=r"(r[2]), "=r"(r[3]) : "r"(addr));
}
__device__ __forceinline__ void cp16(uint32_t dst, const void* src, bool pred) {
    int sz = pred ? 16 : 0;
    asm volatile("cp.async.cg.shared.global [%0], [%1], 16, %2;"
                 :: "r"(dst), "l"(src), "r"(sz) : "memory");
}
#define CP_COMMIT() asm volatile("cp.async.commit_group;" ::: "memory")
#define CP_WAIT(n)  asm volatile("cp.async.wait_group %0;" :: "n"(n) : "memory")

// ================= fp16 mma.sync GEMM, cp.async depth-2 (R9) =================
#define SPITCH_H 40
#define A_HALVES (128 * SPITCH_H)
#define STAGE_HALVES (2 * A_HALVES)
#define STAGEB (STAGE_HALVES * 2)
#define NSTAGE 4

template<int EPI, typename OutT>
__global__ __launch_bounds__(256, 2)
void gemm_h(const __half* __restrict__ A, int lda,
            const __half* __restrict__ Bw, int ldb, int Nact,
            OutT* __restrict__ C, int ldc,
            const float* __restrict__ aux, int K, size_t csplit)
{
    extern __shared__ __half smem[];
    const int tid = threadIdx.x;
    const int wid = tid >> 5;
    const int lane = tid & 31;
    const int g = lane >> 2;
    const int t4 = lane & 3;
    const int warp_m = wid >> 1;
    const int warp_n = wid & 1;
    const int bm = blockIdx.y * 128;
    const int bn = blockIdx.x * 128;

    const int kbase = blockIdx.z * K;
    C += (size_t)blockIdx.z * csplit;

    const int row = tid >> 1;
    const int seg = (tid & 1) << 4;

    const bool bok = (bn + row) < Nact;
    const __half* Ap = A + (size_t)(bm + row) * lda + kbase + seg;
    const __half* Bp = Bw + (size_t)(bn + row) * ldb + kbase + seg;

    uint32_t sbase;
    asm("{ .reg .u64 t; cvta.to.shared.u64 t, %1; cvt.u32.u64 %0, t; }"
        : "=r"(sbase) : "l"(smem));
    const uint32_t dA = sbase + ((uint32_t)row * SPITCH_H + seg) * 2;
    const uint32_t dB = dA + A_HALVES * 2;

    uint32_t aoff[2], boff[4];
#pragma unroll
    for (int mt = 0; mt < 2; mt++)
        aoff[mt] = (((uint32_t)(warp_m * 32 + mt * 16 + (lane & 15))) * SPITCH_H
                    + ((lane >> 4) << 3)) * 2;
#pragma unroll
    for (int nt2 = 0; nt2 < 4; nt2++)
        boff[nt2] = A_HALVES * 2 +
                    (((uint32_t)(warp_n * 64 + nt2 * 16 + (lane & 7) + ((lane >> 4) << 3)))
                     * SPITCH_H + (((lane >> 3) & 1) << 3)) * 2;

    float acc[2][8][4];
#pragma unroll
    for (int mt = 0; mt < 2; mt++)
#pragma unroll
        for (int nt = 0; nt < 8; nt++)
#pragma unroll
            for (int q = 0; q < 4; q++) acc[mt][nt][q] = 0.f;

    const int NC = K >> 5;

    auto issue = [&](int c) {
        const uint32_t so = (uint32_t)(c & (NSTAGE - 1)) * STAGEB;
        const int k0 = c << 5;
        cp16(dA + so,      Ap + k0,     true);
        cp16(dA + so + 16, Ap + k0 + 8, true);
        cp16(dB + so,      Bp + k0,     bok);
        cp16(dB + so + 16, Bp + k0 + 8, bok);
        CP_COMMIT();
    };
    auto compute = [&](int buf) {
        const uint32_t so = sbase + (uint32_t)buf * STAGEB;
#pragma unroll
        for (int ks = 0; ks < 2; ks++) {
            const uint32_t kb = so + ks * 32;
            uint32_t afr[2][4], bfr[4][4];
#pragma unroll
            for (int mt = 0; mt < 2; mt++) ldsm4(afr[mt], kb + aoff[mt]);
#pragma unroll
            for (int nt2 = 0; nt2 < 4; nt2++) ldsm4(bfr[nt2], kb + boff[nt2]);
#pragma unroll
            for (int mt = 0; mt < 2; mt++)
#pragma unroll
                for (int nt2 = 0; nt2 < 4; nt2++) {
                    mma_f16(acc[mt][nt2 * 2],     afr[mt], &bfr[nt2][0]);
                    mma_f16(acc[mt][nt2 * 2 + 1], afr[mt], &bfr[nt2][2]);
                }
        }
    };

    // prologue: depth 2 (R9)
    issue(0);
    if (NC > 1) issue(1);

    for (int c = 0; c < NC; c++) {
        if (c + 1 < NC) CP_WAIT(1);
        else            CP_WAIT(0);
        __syncthreads();
        if (c + 2 < NC) issue(c + 2);
        compute(c & (NSTAGE - 1));
    }

#pragma unroll
    for (int mt = 0; mt < 2; mt++) {
        const int r0 = bm + warp_m * 32 + mt * 16 + g;
#pragma unroll
        for (int nt = 0; nt < 8; nt++) {
            const int col = bn + warp_n * 64 + nt * 8 + 2 * t4;
            if (col >= Nact) continue;
#pragma unroll
            for (int hrow = 0; hrow < 2; hrow++) {
                const int r = r0 + hrow * 8;
                float2 v = make_float2(acc[mt][nt][hrow * 2], acc[mt][nt][hrow * 2 + 1]);
                if (EPI == 1) {
                    float2 bs = *(const float2*)(aux + col);
                    v.x += bs.x; v.y += bs.y;
                    v.x = fmaxf(v.x, 0.f) + log1pf(expf(-fabsf(v.x)));
                    v.y = fmaxf(v.y, 0.f) + log1pf(expf(-fabsf(v.y)));
                } else if (EPI == 2) {
                    float2 rv = *(const float2*)(aux + (size_t)r * ldc + col);
                    v.x += rv.x; v.y += rv.y;
                }
                if (sizeof(OutT) == 2) {
                    *(__half2*)((__half*)C + (size_t)r * ldc + col) = __float22half2_rn(v);
                } else {
                    *(float2*)((float*)C + (size_t)r * ldc + col) = v;
                }
            }
        }
    }
}

// ---------------- fp32 -> fp16 conversion (single buffer) ----------------
__global__ __launch_bounds__(256)
void tohalf_kernel(const float* __restrict__ src, __half* __restrict__ dst, int n4)
{
    int i = blockIdx.x * blockDim.x + threadIdx.x;
    if (i >= n4) return;
    float4 v = ((const float4*)src)[i];
    ((__half2*)dst)[i * 2]     = __floats2half2_rn(v.x, v.y);
    ((__half2*)dst)[i * 2 + 1] = __floats2half2_rn(v.z, v.w);
}

// ---------------- fused cvt of 3 weight buffers ----------------
__global__ __launch_bounds__(256)
void tohalf3_kernel(const float* __restrict__ s0, __half* __restrict__ d0, int n0_4,
                    const float* __restrict__ s1, __half* __restrict__ d1, int n1_4,
                    const float* __restrict__ s2, __half* __restrict__ d2, int n2_4)
{
    int i = blockIdx.x * blockDim.x + threadIdx.x;
    const float* s; __half* d; int j;
    if (i < n0_4)                { s = s0; d = d0; j = i; }
    else if (i < n0_4 + n1_4)    { s = s1; d = d1; j = i - n0_4; }
    else if (i < n0_4 + n1_4 + n2_4) { s = s2; d = d2; j = i - n0_4 - n1_4; }
    else return;
    float4 v = ((const float4*)s)[j];
    ((__half2*)d)[j * 2]     = __floats2half2_rn(v.x, v.y);
    ((__half2*)d)[j * 2 + 1] = __floats2half2_rn(v.z, v.w);
}

// ---------------- split-K reduce -> half xdbl ----------------
__global__ __launch_bounds__(256)
void reduce_split_kernel()
{
    int idx = blockIdx.x * blockDim.x + threadIdx.x;
    if (idx >= BL * XDBL_W) return;
    float s = 0.f;
#pragma unroll
    for (int k = 0; k < SPLITK; k++)
        s += g_part[(size_t)k * BL * XDBL_W + idx];
    g_xdbl_h[idx] = __float2half_rn(s);
}

// ---------------- causal depthwise conv + bias + SiLU (half2, 2 ch/thread) ----------------
__global__ __launch_bounds__(256)
void conv_silu_kernel(const float* __restrict__ cw, const float* __restrict__ cb)
{
    int idx = blockIdx.x * blockDim.x + threadIdx.x;
    if (idx >= BL * D_INNER / 2) return;
    int dp = idx & (D_INNER / 2 - 1);
    int d = dp << 1;
    int row = idx >> 10;
    int l = row & (LSEQ - 1);

    float4 wa = *(const float4*)(cw + d * 4);
    float4 wb = *(const float4*)(cw + d * 4 + 4);
    float2 bias = *(const float2*)(cb + d);
    float a0 = bias.x, a1 = bias.y;

    const __half2* src = (const __half2*)g_xzh + dp;
#pragma unroll
    for (int j = 0; j < 4; j++) {
        int lj = l - 3 + j;
        if (lj >= 0) {
            float2 v = __half22float2(src[(size_t)(row - 3 + j) * 2048]);
            float w0 = (j == 0) ? wa.x : (j == 1) ? wa.y : (j == 2) ? wa.z : wa.w;
            float w1 = (j == 0) ? wb.x : (j == 1) ? wb.y : (j == 2) ? wb.z : wb.w;
            a0 = fmaf(v.x, w0, a0);
            a1 = fmaf(v.y, w1, a1);
        }
    }
    float s0 = a0 / (1.f + __expf(-a0));
    float s1 = a1 / (1.f + __expf(-a1));
    ((__half2*)g_uh)[idx] = __floats2half2_rn(s0, s1);
}

// ---------------- selective scan: 8 lanes/channel, 2 states/lane (R9 shape) ----------------
// 4-step groups, level-batched shfl, distance-2 group prefetch.
// 128 threads / 16 channels per block; 256 blocks covers all 148 SMs.
__global__ __launch_bounds__(128)
void scan_kernel(const float* __restrict__ A_log, const float* __restrict__ Dp)
{
    const int tid = threadIdx.x;
    const int ch = blockIdx.x * 16 + (tid >> 3);
    const int b = ch >> 11;
    const int d = ch & (D_INNER - 1);
    const int ls = tid & 7;
    const int n0 = ls << 1;

    const float A0 = -expf(A_log[d * D_STATE + n0]);
    const float A1 = -expf(A_log[d * D_STATE + n0 + 1]);
    const float Dd = Dp[d];

    float h0 = 0.f, h1 = 0.f;
    const __half* xd = g_xdbl_h + (size_t)b * LSEQ * XDBL_W + DT_RANK + n0;
    const size_t base2 = (size_t)b * LSEQ * D_INNER + d;
    const size_t basez = (size_t)b * LSEQ * (2 * D_INNER) + D_INNER + d;

    auto load_group = [&](int l, float* D_, float* U_, float* Z_, float2* B_, float2* C_) {
#pragma unroll
        for (int j = 0; j < 4; j++) {
            size_t o2 = base2 + (size_t)(l + j) * D_INNER;
            D_[j] = __half2float(g_deltah[o2]);
            U_[j] = __half2float(g_uh[o2]);
        }
        if (ls == 0) {
#pragma unroll
            for (int j = 0; j < 4; j++)
                Z_[j] = __half2float(g_xzh[basez + (size_t)(l + j) * (2 * D_INNER)]);
        }
#pragma unroll
        for (int j = 0; j < 4; j++) {
            const __half* xr = xd + (size_t)(l + j) * XDBL_W;
            B_[j] = __half22float2(*(const __half2*)(xr));
            C_[j] = __half22float2(*(const __half2*)(xr + D_STATE));
        }
    };

    auto proc = [&](int l0, const float* D_, const float* U_, const float* Z_,
                    const float2* B_, const float2* C_) {
        float yp[4];
#pragma unroll
        for (int j = 0; j < 4; j++) {
            float e0 = __expf(D_[j] * A0);
            float e1 = __expf(D_[j] * A1);
            float du = D_[j] * U_[j];
            h0 = fmaf(e0, h0, du * B_[j].x);
            h1 = fmaf(e1, h1, du * B_[j].y);
            yp[j] = fmaf(h0, C_[j].x, h1 * C_[j].y);
        }
#pragma unroll
        for (int j = 0; j < 4; j++) yp[j] += __shfl_xor_sync(0xffffffffu, yp[j], 1);
#pragma unroll
        for (int j = 0; j < 4; j++) yp[j] += __shfl_xor_sync(0xffffffffu, yp[j], 2);
#pragma unroll
        for (int j = 0; j < 4; j++) yp[j] += __shfl_xor_sync(0xffffffffu, yp[j], 4);
        if (ls == 0) {
#pragma unroll
            for (int j = 0; j < 4; j++) {
                float z = Z_[j];
                float sz = z / (1.f + __expf(-z));
                g_yh[base2 + (size_t)(l0 + j) * D_INNER] =
                    __float2half_rn(fmaf(U_[j], Dd, yp[j]) * sz);
            }
        }
    };

    float aD[4], aU[4], aZ[4]; float2 aB[4], aC[4];
    float bD[4], bU[4], bZ[4]; float2 bB[4], bC[4];
    float tD[4], tU[4], tZ[4]; float2 tB[4], tC[4];
    float sD[4], sU[4], sZ[4]; float2 sB[4], sC[4];

    load_group(0, aD, aU, aZ, aB, aC);
    load_group(4, bD, bU, bZ, bB, bC);

    for (int l0 = 0; l0 < LSEQ; l0 += 8) {
        const bool more = (l0 + 8) < LSEQ;
        if (more) {
            load_group(l0 + 8,  tD, tU, tZ, tB, tC);
            load_group(l0 + 12, sD, sU, sZ, sB, sC);
        }
        proc(l0,     aD, aU, aZ, aB, aC);
        proc(l0 + 4, bD, bU, bZ, bB, bC);
        if (more) {
#pragma unroll
            for (int j = 0; j < 4; j++) {
                aD[j] = tD[j]; aU[j] = tU[j]; aZ[j] = tZ[j]; aB[j] = tB[j]; aC[j] = tC[j];
                bD[j] = sD[j]; bU[j] = sU[j]; bZ[j] = sZ[j]; bB[j] = sB[j]; bC[j] = sC[j];
            }
        }
    }
}

// ---------------- LayerNorm over last dim (1024) ----------------
__global__ __launch_bounds__(256)
void ln_kernel(const float* __restrict__ lnw, const float* __restrict__ lnb,
               float* __restrict__ out)
{
    int row = blockIdx.x;
    const float* hp = g_h + (size_t)row * D_MODEL;
    int tid = threadIdx.x;

    float v[4];
    float s = 0.f, sq = 0.f;
#pragma unroll
    for (int i = 0; i < 4; i++) {
        v[i] = hp[tid + i * 256];
        s += v[i];
        sq += v[i] * v[i];
    }
#pragma unroll
    for (int off = 16; off; off >>= 1) {
        s += __shfl_xor_sync(0xffffffffu, s, off);
        sq += __shfl_xor_sync(0xffffffffu, sq, off);
    }
    __shared__ float ss[8], ssq[8];
    __shared__ float mu_s, rs_s;
    if ((tid & 31) == 0) { ss[tid >> 5] = s; ssq[tid >> 5] = sq; }
    __syncthreads();
    if (tid == 0) {
        float S = 0.f, SQ = 0.f;
#pragma unroll
        for (int i = 0; i < 8; i++) { S += ss[i]; SQ += ssq[i]; }
        float mu = S * (1.f / D_MODEL);
        float var = SQ * (1.f / D_MODEL) - mu * mu;
        mu_s = mu;
        rs_s = rsqrtf(var + 1e-5f);
    }
    __syncthreads();
    float mu = mu_s, rs = rs_s;
#pragma unroll
    for (int i = 0; i < 4; i++) {
        int c = tid + i * 256;
        out[(size_t)row * D_MODEL + c] = (v[i] - mu) * rs * lnw[c] + lnb[c];
    }
}

// ---------------- host launch ----------------
extern "C" void kernel_launch(void* const* d_in, const int* in_sizes, int n_in,
                              void* d_out, int out_size)
{
    const float* x          = (const float*)d_in[0];
    const float* in_proj_w  = (const float*)d_in[1];
    const float* conv_w     = (const float*)d_in[2];
    const float* conv_b     = (const float*)d_in[3];
    const float* x_proj_w   = (const float*)d_in[4];
    const float* dt_proj_w  = (const float*)d_in[5];
    const float* dt_proj_b  = (const float*)d_in[6];
    const float* A_log      = (const float*)d_in[7];
    const float* Dp         = (const float*)d_in[8];
    const float* out_proj_w = (const float*)d_in[9];
    const float* ln_w       = (const float*)d_in[10];
    const float* ln_b       = (const float*)d_in[11];
    float* out = (float*)d_out;

    float *p_h, *p_part;
    __half *p_xzh, *p_deltah, *p_uh, *p_xdblh, *p_yh, *p_xh;
    __half *p_w1h, *p_w3h, *p_w4h, *p_w6h;
    cudaGetSymbolAddress((void**)&p_h,      g_h);
    cudaGetSymbolAddress((void**)&p_part,   g_part);
    cudaGetSymbolAddress((void**)&p_xzh,    g_xzh);
    cudaGetSymbolAddress((void**)&p_deltah, g_deltah);
    cudaGetSymbolAddress((void**)&p_uh,     g_uh);
    cudaGetSymbolAddress((void**)&p_xdblh,  g_xdbl_h);
    cudaGetSymbolAddress((void**)&p_yh,     g_yh);
    cudaGetSymbolAddress((void**)&p_xh,     g_xh);
    cudaGetSymbolAddress((void**)&p_w1h,    g_w1h);
    cudaGetSymbolAddress((void**)&p_w3h,    g_w3h);
    cudaGetSymbolAddress((void**)&p_w4h,    g_w4h);
    cudaGetSymbolAddress((void**)&p_w6h,    g_w6h);

    const int smemB = NSTAGE * STAGEB;   // 81920
    cudaFuncSetAttribute((const void*)gemm_h<0, __half>, cudaFuncAttributeMaxDynamicSharedMemorySize, smemB);
    cudaFuncSetAttribute((const void*)gemm_h<0, float>,  cudaFuncAttributeMaxDynamicSharedMemorySize, smemB);
    cudaFuncSetAttribute((const void*)gemm_h<1, __half>, cudaFuncAttributeMaxDynamicSharedMemorySize, smemB);
    cudaFuncSetAttribute((const void*)gemm_h<2, float>,  cudaFuncAttributeMaxDynamicSharedMemorySize, smemB);

    // launch 0: cvt x; launch 1: cvt w1; launch 2: fused cvt w3/w4/w6
    {
        int nx4 = (BL * D_MODEL) / 4;
        tohalf_kernel<<<(nx4 + 255) / 256, 256>>>(x, p_xh, nx4);
        int nw1_4 = (2 * D_INNER * D_MODEL) / 4;
        tohalf_kernel<<<(nw1_4 + 255) / 256, 256>>>(in_proj_w, p_w1h, nw1_4);
        int n3 = (XDBL_W * D_INNER) / 4;
        int n4 = (D_INNER * DT_RANK) / 4;
        int n6 = (D_MODEL * D_INNER) / 4;
        tohalf3_kernel<<<(n3 + n4 + n6 + 255) / 256, 256>>>(
            x_proj_w, p_w3h, n3, dt_proj_w, p_w4h, n4, out_proj_w, p_w6h, n6);
    }

    // 1) xz = x @ in_proj_w^T [4096,4096] K=1024 -> half  (launch 3 = profiled control)
    gemm_h<0, __half><<<dim3(32, 32), 256, smemB>>>(
        p_xh, D_MODEL, p_w1h, D_MODEL, 2 * D_INNER,
        p_xzh, 2 * D_INNER, nullptr, D_MODEL, 0);

    // 2) u = silu(causal_conv(xi) + cb) -> half
    conv_silu_kernel<<<(BL * D_INNER / 2 + 255) / 256, 256>>>(conv_w, conv_b);
    // 3) x_dbl = u @ x_proj_w^T [4096,96], split-K x8 + reduce -> half
    gemm_h<0, float><<<dim3(1, 32, SPLITK), 256, smemB>>>(
        p_uh, D_INNER, p_w3h, D_INNER, XDBL_W,
        p_part, XDBL_W, nullptr, D_INNER / SPLITK, (size_t)BL * XDBL_W);
    reduce_split_kernel<<<(BL * XDBL_W + 255) / 256, 256>>>();
    // 4) delta = softplus(dt @ dt_proj_w^T + b) [4096,2048] K=64 -> half
    gemm_h<1, __half><<<dim3(16, 32), 256, smemB>>>(
        p_xdblh, XDBL_W, p_w4h, DT_RANK, D_INNER,
        p_deltah, D_INNER, dt_proj_b, DT_RANK, 0);
    // 5) selective scan + skip + gate -> half y (256 blocks x 128 thr: full-chip spread)
    scan_kernel<<<256, 128>>>(A_log, Dp);
    // 6) h = y @ out_proj_w^T + x [4096,1024] K=2048 -> float
    gemm_h<2, float><<<dim3(8, 32), 256, smemB>>>(
        p_yh, D_INNER, p_w6h, D_INNER, D_MODEL,
        p_h, D_MODEL, x, D_INNER, 0);
    // 7) LayerNorm -> out
    ln_kernel<<<BL, 256>>>(ln_w, ln_b, out);
}

// round 14
// speedup vs baseline: 1.1332x; 1.0119x over previous
#include <cuda_runtime.h>
#include <cuda_fp16.h>
#include <math.h>
#include <stdint.h>

#define D_MODEL 1024
#define D_INNER 2048
#define D_STATE 16
#define DT_RANK 64
#define NB 2
#define LSEQ 2048
#define BL (NB*LSEQ)            /* 4096 rows total */
#define XDBL_W 96
#define SPLITK 8
#define SPLITK6 2

// ---------------- scratch (device globals) ----------------
__device__ float  g_part[(size_t)SPLITK * BL * XDBL_W];    // GEMM3 split-K partials
__device__ float  g_part6[(size_t)SPLITK6 * BL * D_MODEL]; // GEMM6 split-K partials
// fp16 buffers (16B-aligned for cp.async)
__device__ __align__(16) __half g_xzh[(size_t)BL * 2 * D_INNER];
__device__ __align__(16) __half g_deltah[(size_t)BL * D_INNER];
__device__ __align__(16) __half g_uh[(size_t)BL * D_INNER];
__device__ __align__(16) __half g_xdbl_h[(size_t)BL * XDBL_W];  // [dt(64) | BC interleaved(32)]
__device__ __align__(16) __half g_yh[(size_t)BL * D_INNER];
__device__ __align__(16) __half g_xh[(size_t)BL * D_MODEL];
__device__ __align__(16) __half g_w1h[(size_t)2 * D_INNER * D_MODEL];
__device__ __align__(16) __half g_w3h[(size_t)XDBL_W * D_INNER];
__device__ __align__(16) __half g_w4h[(size_t)D_INNER * DT_RANK];
__device__ __align__(16) __half g_w6h[(size_t)D_MODEL * D_INNER];

__device__ __forceinline__ void mma_f16(float* d, const uint32_t* a, const uint32_t* b) {
    asm volatile(
        "mma.sync.aligned.m16n8k16.row.col.f32.f16.f16.f32 "
        "{%0,%1,%2,%3}, {%4,%5,%6,%7}, {%8,%9}, {%0,%1,%2,%3};"
        : "+f"(d[0]), "+f"(d[1]), "+f"(d[2]), "+f"(d[3])
        : "r"(a[0]), "r"(a[1]), "r"(a[2]), "r"(a[3]), "r"(b[0]), "r"(b[1]));
}
__device__ __forceinline__ void ldsm4(uint32_t* r, uint32_t addr) {
    asm volatile("ldmatrix.sync.aligned.m8n8.x4.shared.b16 {%0,%1,%2,%3}, [%4];"
                 : "=r"(r[0]), "=r"(r[1]), "=r"(r[2]), "=r"(r[3]) : "r"(addr));
}
__device__ __forceinline__ void cp16(uint32_t dst, const void* src, bool pred) {
    int sz = pred ? 16 : 0;
    asm volatile("cp.async.cg.shared.global [%0], [%1], 16, %2;"
                 :: "r"(dst), "l"(src), "r"(sz) : "memory");
}
#define CP_COMMIT() asm volatile("cp.async.commit_group;" ::: "memory")
#define CP_WAIT(n)  asm volatile("cp.async.wait_group %0;" :: "n"(n) : "memory")

// ================= fp16 mma.sync GEMM, cp.async depth-2 (R9/R13) =================
#define SPITCH_H 40
#define A_HALVES (128 * SPITCH_H)
#define STAGE_HALVES (2 * A_HALVES)
#define STAGEB (STAGE_HALVES * 2)
#define NSTAGE 4

template<int EPI, typename OutT>
__global__ __launch_bounds__(256, 2)
void gemm_h(const __half* __restrict__ A, int lda,
            const __half* __restrict__ Bw, int ldb, int Nact,
            OutT* __restrict__ C, int ldc,
            const float* __restrict__ aux, int K, size_t csplit)
{
    extern __shared__ __half smem[];
    const int tid = threadIdx.x;
    const int wid = tid >> 5;
    const int lane = tid & 31;
    const int g = lane >> 2;
    const int t4 = lane & 3;
    const int warp_m = wid >> 1;
    const int warp_n = wid & 1;
    const int bm = blockIdx.y * 128;
    const int bn = blockIdx.x * 128;

    const int kbase = blockIdx.z * K;
    C += (size_t)blockIdx.z * csplit;

    const int row = tid >> 1;
    const int seg = (tid & 1) << 4;

    const bool bok = (bn + row) < Nact;
    const __half* Ap = A + (size_t)(bm + row) * lda + kbase + seg;
    const __half* Bp = Bw + (size_t)(bn + row) * ldb + kbase + seg;

    uint32_t sbase;
    asm("{ .reg .u64 t; cvta.to.shared.u64 t, %1; cvt.u32.u64 %0, t; }"
        : "=r"(sbase) : "l"(smem));
    const uint32_t dA = sbase + ((uint32_t)row * SPITCH_H + seg) * 2;
    const uint32_t dB = dA + A_HALVES * 2;

    uint32_t aoff[2], boff[4];
#pragma unroll
    for (int mt = 0; mt < 2; mt++)
        aoff[mt] = (((uint32_t)(warp_m * 32 + mt * 16 + (lane & 15))) * SPITCH_H
                    + ((lane >> 4) << 3)) * 2;
#pragma unroll
    for (int nt2 = 0; nt2 < 4; nt2++)
        boff[nt2] = A_HALVES * 2 +
                    (((uint32_t)(warp_n * 64 + nt2 * 16 + (lane & 7) + ((lane >> 4) << 3)))
                     * SPITCH_H + (((lane >> 3) & 1) << 3)) * 2;

    float acc[2][8][4];
#pragma unroll
    for (int mt = 0; mt < 2; mt++)
#pragma unroll
        for (int nt = 0; nt < 8; nt++)
#pragma unroll
            for (int q = 0; q < 4; q++) acc[mt][nt][q] = 0.f;

    const int NC = K >> 5;

    auto issue = [&](int c) {
        const uint32_t so = (uint32_t)(c & (NSTAGE - 1)) * STAGEB;
        const int k0 = c << 5;
        cp16(dA + so,      Ap + k0,     true);
        cp16(dA + so + 16, Ap + k0 + 8, true);
        cp16(dB + so,      Bp + k0,     bok);
        cp16(dB + so + 16, Bp + k0 + 8, bok);
        CP_COMMIT();
    };
    auto compute = [&](int buf) {
        const uint32_t so = sbase + (uint32_t)buf * STAGEB;
#pragma unroll
        for (int ks = 0; ks < 2; ks++) {
            const uint32_t kb = so + ks * 32;
            uint32_t afr[2][4], bfr[4][4];
#pragma unroll
            for (int mt = 0; mt < 2; mt++) ldsm4(afr[mt], kb + aoff[mt]);
#pragma unroll
            for (int nt2 = 0; nt2 < 4; nt2++) ldsm4(bfr[nt2], kb + boff[nt2]);
#pragma unroll
            for (int mt = 0; mt < 2; mt++)
#pragma unroll
                for (int nt2 = 0; nt2 < 4; nt2++) {
                    mma_f16(acc[mt][nt2 * 2],     afr[mt], &bfr[nt2][0]);
                    mma_f16(acc[mt][nt2 * 2 + 1], afr[mt], &bfr[nt2][2]);
                }
        }
    };

    issue(0);
    if (NC > 1) issue(1);

    for (int c = 0; c < NC; c++) {
        if (c + 1 < NC) CP_WAIT(1);
        else            CP_WAIT(0);
        __syncthreads();
        if (c + 2 < NC) issue(c + 2);
        compute(c & (NSTAGE - 1));
    }

#pragma unroll
    for (int mt = 0; mt < 2; mt++) {
        const int r0 = bm + warp_m * 32 + mt * 16 + g;
#pragma unroll
        for (int nt = 0; nt < 8; nt++) {
            const int col = bn + warp_n * 64 + nt * 8 + 2 * t4;
            if (col >= Nact) continue;
#pragma unroll
            for (int hrow = 0; hrow < 2; hrow++) {
                const int r = r0 + hrow * 8;
                float2 v = make_float2(acc[mt][nt][hrow * 2], acc[mt][nt][hrow * 2 + 1]);
                if (EPI == 1) {
                    float2 bs = *(const float2*)(aux + col);
                    v.x += bs.x; v.y += bs.y;
                    v.x = fmaxf(v.x, 0.f) + log1pf(expf(-fabsf(v.x)));
                    v.y = fmaxf(v.y, 0.f) + log1pf(expf(-fabsf(v.y)));
                }
                if (sizeof(OutT) == 2) {
                    *(__half2*)((__half*)C + (size_t)r * ldc + col) = __float22half2_rn(v);
                } else {
                    *(float2*)((float*)C + (size_t)r * ldc + col) = v;
                }
            }
        }
    }
}

// ---------------- fp32 -> fp16 conversion ----------------
__global__ __launch_bounds__(256)
void tohalf_kernel(const float* __restrict__ src, __half* __restrict__ dst, int n4)
{
    int i = blockIdx.x * blockDim.x + threadIdx.x;
    if (i >= n4) return;
    float4 v = ((const float4*)src)[i];
    ((__half2*)dst)[i * 2]     = __floats2half2_rn(v.x, v.y);
    ((__half2*)dst)[i * 2 + 1] = __floats2half2_rn(v.z, v.w);
}

// ---------------- fused cvt of 3 weight buffers ----------------
__global__ __launch_bounds__(256)
void tohalf3_kernel(const float* __restrict__ s0, __half* __restrict__ d0, int n0_4,
                    const float* __restrict__ s1, __half* __restrict__ d1, int n1_4,
                    const float* __restrict__ s2, __half* __restrict__ d2, int n2_4)
{
    int i = blockIdx.x * blockDim.x + threadIdx.x;
    const float* s; __half* d; int j;
    if (i < n0_4)                { s = s0; d = d0; j = i; }
    else if (i < n0_4 + n1_4)    { s = s1; d = d1; j = i - n0_4; }
    else if (i < n0_4 + n1_4 + n2_4) { s = s2; d = d2; j = i - n0_4 - n1_4; }
    else return;
    float4 v = ((const float4*)s)[j];
    ((__half2*)d)[j * 2]     = __floats2half2_rn(v.x, v.y);
    ((__half2*)d)[j * 2 + 1] = __floats2half2_rn(v.z, v.w);
}

// ---------------- split-K reduce -> half xdbl with BC interleave ----------------
// output layout per row: cols 0..63 = dt; cols 64+ls*4+{0,1} = B[2ls,2ls+1];
// cols 64+ls*4+{2,3} = C[2ls,2ls+1]  (ls = 0..7)
__global__ __launch_bounds__(256)
void reduce_split_kernel()
{
    int idx = blockIdx.x * blockDim.x + threadIdx.x;
    if (idx >= BL * XDBL_W) return;
    float s = 0.f;
#pragma unroll
    for (int k = 0; k < SPLITK; k++)
        s += g_part[(size_t)k * BL * XDBL_W + idx];
    int row = idx / XDBL_W;
    int c = idx - row * XDBL_W;
    int oc;
    if (c < DT_RANK) {
        oc = c;
    } else if (c < DT_RANK + D_STATE) {             // B
        int nb = c - DT_RANK;
        oc = DT_RANK + (nb >> 1) * 4 + (nb & 1);
    } else {                                         // C
        int nc = c - DT_RANK - D_STATE;
        oc = DT_RANK + (nc >> 1) * 4 + 2 + (nc & 1);
    }
    g_xdbl_h[(size_t)row * XDBL_W + oc] = __float2half_rn(s);
}

// ---------------- causal depthwise conv + bias + SiLU (half2, 2 ch/thread) ----------------
__global__ __launch_bounds__(256)
void conv_silu_kernel(const float* __restrict__ cw, const float* __restrict__ cb)
{
    int idx = blockIdx.x * blockDim.x + threadIdx.x;
    if (idx >= BL * D_INNER / 2) return;
    int dp = idx & (D_INNER / 2 - 1);
    int d = dp << 1;
    int row = idx >> 10;
    int l = row & (LSEQ - 1);

    float4 wa = *(const float4*)(cw + d * 4);
    float4 wb = *(const float4*)(cw + d * 4 + 4);
    float2 bias = *(const float2*)(cb + d);
    float a0 = bias.x, a1 = bias.y;

    const __half2* src = (const __half2*)g_xzh + dp;
#pragma unroll
    for (int j = 0; j < 4; j++) {
        int lj = l - 3 + j;
        if (lj >= 0) {
            float2 v = __half22float2(src[(size_t)(row - 3 + j) * 2048]);
            float w0 = (j == 0) ? wa.x : (j == 1) ? wa.y : (j == 2) ? wa.z : wa.w;
            float w1 = (j == 0) ? wb.x : (j == 1) ? wb.y : (j == 2) ? wb.z : wb.w;
            a0 = fmaf(v.x, w0, a0);
            a1 = fmaf(v.y, w1, a1);
        }
    }
    float s0 = a0 / (1.f + __expf(-a0));
    float s1 = a1 / (1.f + __expf(-a1));
    ((__half2*)g_uh)[idx] = __floats2half2_rn(s0, s1);
}

// ---------------- selective scan: 8 lanes/channel, 2 states/lane (R13 shape) ----------------
// BC loaded as one uint2 (B0,B1,C0,C1) per lane per step.
__global__ __launch_bounds__(128)
void scan_kernel(const float* __restrict__ A_log, const float* __restrict__ Dp)
{
    const int tid = threadIdx.x;
    const int ch = blockIdx.x * 16 + (tid >> 3);
    const int b = ch >> 11;
    const int d = ch & (D_INNER - 1);
    const int ls = tid & 7;
    const int n0 = ls << 1;

    const float A0 = -expf(A_log[d * D_STATE + n0]);
    const float A1 = -expf(A_log[d * D_STATE + n0 + 1]);
    const float Dd = Dp[d];

    float h0 = 0.f, h1 = 0.f;
    // interleaved BC: lane ls reads 4 halves at DT_RANK + ls*4
    const __half* xd = g_xdbl_h + (size_t)b * LSEQ * XDBL_W + DT_RANK + ls * 4;
    const size_t base2 = (size_t)b * LSEQ * D_INNER + d;
    const size_t basez = (size_t)b * LSEQ * (2 * D_INNER) + D_INNER + d;

    auto load_group = [&](int l, float* D_, float* U_, float* Z_, float2* B_, float2* C_) {
#pragma unroll
        for (int j = 0; j < 4; j++) {
            size_t o2 = base2 + (size_t)(l + j) * D_INNER;
            D_[j] = __half2float(g_deltah[o2]);
            U_[j] = __half2float(g_uh[o2]);
        }
        if (ls == 0) {
#pragma unroll
            for (int j = 0; j < 4; j++)
                Z_[j] = __half2float(g_xzh[basez + (size_t)(l + j) * (2 * D_INNER)]);
        }
#pragma unroll
        for (int j = 0; j < 4; j++) {
            uint2 bc = *(const uint2*)(xd + (size_t)(l + j) * XDBL_W);
            B_[j] = __half22float2(*(const __half2*)&bc.x);
            C_[j] = __half22float2(*(const __half2*)&bc.y);
        }
    };

    auto proc = [&](int l0, const float* D_, const float* U_, const float* Z_,
                    const float2* B_, const float2* C_) {
        float yp[4];
#pragma unroll
        for (int j = 0; j < 4; j++) {
            float e0 = __expf(D_[j] * A0);
            float e1 = __expf(D_[j] * A1);
            float du = D_[j] * U_[j];
            h0 = fmaf(e0, h0, du * B_[j].x);
            h1 = fmaf(e1, h1, du * B_[j].y);
            yp[j] = fmaf(h0, C_[j].x, h1 * C_[j].y);
        }
#pragma unroll
        for (int j = 0; j < 4; j++) yp[j] += __shfl_xor_sync(0xffffffffu, yp[j], 1);
#pragma unroll
        for (int j = 0; j < 4; j++) yp[j] += __shfl_xor_sync(0xffffffffu, yp[j], 2);
#pragma unroll
        for (int j = 0; j < 4; j++) yp[j] += __shfl_xor_sync(0xffffffffu, yp[j], 4);
        if (ls == 0) {
#pragma unroll
            for (int j = 0; j < 4; j++) {
                float z = Z_[j];
                float sz = z / (1.f + __expf(-z));
                g_yh[base2 + (size_t)(l0 + j) * D_INNER] =
                    __float2half_rn(fmaf(U_[j], Dd, yp[j]) * sz);
            }
        }
    };

    float aD[4], aU[4], aZ[4]; float2 aB[4], aC[4];
    float bD[4], bU[4], bZ[4]; float2 bB[4], bC[4];
    float tD[4], tU[4], tZ[4]; float2 tB[4], tC[4];
    float sD[4], sU[4], sZ[4]; float2 sB[4], sC[4];

    load_group(0, aD, aU, aZ, aB, aC);
    load_group(4, bD, bU, bZ, bB, bC);

    for (int l0 = 0; l0 < LSEQ; l0 += 8) {
        const bool more = (l0 + 8) < LSEQ;
        if (more) {
            load_group(l0 + 8,  tD, tU, tZ, tB, tC);
            load_group(l0 + 12, sD, sU, sZ, sB, sC);
        }
        proc(l0,     aD, aU, aZ, aB, aC);
        proc(l0 + 4, bD, bU, bZ, bB, bC);
        if (more) {
#pragma unroll
            for (int j = 0; j < 4; j++) {
                aD[j] = tD[j]; aU[j] = tU[j]; aZ[j] = tZ[j]; aB[j] = tB[j]; aC[j] = tC[j];
                bD[j] = sD[j]; bU[j] = sU[j]; bZ[j] = sZ[j]; bB[j] = sB[j]; bC[j] = sC[j];
            }
        }
    }
}

// ---------------- fused GEMM6-reduce + residual + LayerNorm ----------------
__global__ __launch_bounds__(256)
void reduce_ln_kernel(const float* __restrict__ x,
                      const float* __restrict__ lnw, const float* __restrict__ lnb,
                      float* __restrict__ out)
{
    int row = blockIdx.x;
    int tid = threadIdx.x;
    const float* p0 = g_part6 + (size_t)row * D_MODEL;
    const float* p1 = g_part6 + (size_t)BL * D_MODEL + (size_t)row * D_MODEL;
    const float* xr = x + (size_t)row * D_MODEL;

    float v[4];
    float s = 0.f, sq = 0.f;
#pragma unroll
    for (int i = 0; i < 4; i++) {
        int c = tid + i * 256;
        v[i] = p0[c] + p1[c] + xr[c];
        s += v[i];
        sq += v[i] * v[i];
    }
#pragma unroll
    for (int off = 16; off; off >>= 1) {
        s += __shfl_xor_sync(0xffffffffu, s, off);
        sq += __shfl_xor_sync(0xffffffffu, sq, off);
    }
    __shared__ float ss[8], ssq[8];
    __shared__ float mu_s, rs_s;
    if ((tid & 31) == 0) { ss[tid >> 5] = s; ssq[tid >> 5] = sq; }
    __syncthreads();
    if (tid == 0) {
        float S = 0.f, SQ = 0.f;
#pragma unroll
        for (int i = 0; i < 8; i++) { S += ss[i]; SQ += ssq[i]; }
        float mu = S * (1.f / D_MODEL);
        float var = SQ * (1.f / D_MODEL) - mu * mu;
        mu_s = mu;
        rs_s = rsqrtf(var + 1e-5f);
    }
    __syncthreads();
    float mu = mu_s, rs = rs_s;
#pragma unroll
    for (int i = 0; i < 4; i++) {
        int c = tid + i * 256;
        out[(size_t)row * D_MODEL + c] = (v[i] - mu) * rs * lnw[c] + lnb[c];
    }
}

// ---------------- host launch ----------------
extern "C" void kernel_launch(void* const* d_in, const int* in_sizes, int n_in,
                              void* d_out, int out_size)
{
    const float* x          = (const float*)d_in[0];
    const float* in_proj_w  = (const float*)d_in[1];
    const float* conv_w     = (const float*)d_in[2];
    const float* conv_b     = (const float*)d_in[3];
    const float* x_proj_w   = (const float*)d_in[4];
    const float* dt_proj_w  = (const float*)d_in[5];
    const float* dt_proj_b  = (const float*)d_in[6];
    const float* A_log      = (const float*)d_in[7];
    const float* Dp         = (const float*)d_in[8];
    const float* out_proj_w = (const float*)d_in[9];
    const float* ln_w       = (const float*)d_in[10];
    const float* ln_b       = (const float*)d_in[11];
    float* out = (float*)d_out;

    float *p_part, *p_part6;
    __half *p_xzh, *p_deltah, *p_uh, *p_xdblh, *p_yh, *p_xh;
    __half *p_w1h, *p_w3h, *p_w4h, *p_w6h;
    cudaGetSymbolAddress((void**)&p_part,   g_part);
    cudaGetSymbolAddress((void**)&p_part6,  g_part6);
    cudaGetSymbolAddress((void**)&p_xzh,    g_xzh);
    cudaGetSymbolAddress((void**)&p_deltah, g_deltah);
    cudaGetSymbolAddress((void**)&p_uh,     g_uh);
    cudaGetSymbolAddress((void**)&p_xdblh,  g_xdbl_h);
    cudaGetSymbolAddress((void**)&p_yh,     g_yh);
    cudaGetSymbolAddress((void**)&p_xh,     g_xh);
    cudaGetSymbolAddress((void**)&p_w1h,    g_w1h);
    cudaGetSymbolAddress((void**)&p_w3h,    g_w3h);
    cudaGetSymbolAddress((void**)&p_w4h,    g_w4h);
    cudaGetSymbolAddress((void**)&p_w6h,    g_w6h);

    const int smemB = NSTAGE * STAGEB;   // 81920
    cudaFuncSetAttribute((const void*)gemm_h<0, __half>, cudaFuncAttributeMaxDynamicSharedMemorySize, smemB);
    cudaFuncSetAttribute((const void*)gemm_h<0, float>,  cudaFuncAttributeMaxDynamicSharedMemorySize, smemB);
    cudaFuncSetAttribute((const void*)gemm_h<1, __half>, cudaFuncAttributeMaxDynamicSharedMemorySize, smemB);

    // launch 0: cvt x; 1: cvt w1; 2: fused cvt w3/w4/w6
    {
        int nx4 = (BL * D_MODEL) / 4;
        tohalf_kernel<<<(nx4 + 255) / 256, 256>>>(x, p_xh, nx4);
        int nw1_4 = (2 * D_INNER * D_MODEL) / 4;
        tohalf_kernel<<<(nw1_4 + 255) / 256, 256>>>(in_proj_w, p_w1h, nw1_4);
        int n3 = (XDBL_W * D_INNER) / 4;
        int n4 = (D_INNER * DT_RANK) / 4;
        int n6 = (D_MODEL * D_INNER) / 4;
        tohalf3_kernel<<<(n3 + n4 + n6 + 255) / 256, 256>>>(
            x_proj_w, p_w3h, n3, dt_proj_w, p_w4h, n4, out_proj_w, p_w6h, n6);
    }

    // 1) xz = x @ in_proj_w^T [4096,4096] K=1024 -> half  (launch 3 = profiled control)
    gemm_h<0, __half><<<dim3(32, 32), 256, smemB>>>(
        p_xh, D_MODEL, p_w1h, D_MODEL, 2 * D_INNER,
        p_xzh, 2 * D_INNER, nullptr, D_MODEL, 0);

    // 2) u = silu(causal_conv(xi) + cb) -> half
    conv_silu_kernel<<<(BL * D_INNER / 2 + 255) / 256, 256>>>(conv_w, conv_b);
    // 3) x_dbl = u @ x_proj_w^T [4096,96], split-K x8 + reduce (BC interleave) -> half
    gemm_h<0, float><<<dim3(1, 32, SPLITK), 256, smemB>>>(
        p_uh, D_INNER, p_w3h, D_INNER, XDBL_W,
        p_part, XDBL_W, nullptr, D_INNER / SPLITK, (size_t)BL * XDBL_W);
    reduce_split_kernel<<<(BL * XDBL_W + 255) / 256, 256>>>();
    // 4) delta = softplus(dt @ dt_proj_w^T + b) [4096,2048] K=64 -> half
    gemm_h<1, __half><<<dim3(16, 32), 256, smemB>>>(
        p_xdblh, XDBL_W, p_w4h, DT_RANK, D_INNER,
        p_deltah, D_INNER, dt_proj_b, DT_RANK, 0);
    // 5) selective scan + skip + gate -> half y
    scan_kernel<<<256, 128>>>(A_log, Dp);
    // 6) h-partials = y @ out_proj_w^T, split-K x2 [4096,1024]
    gemm_h<0, float><<<dim3(8, 32, SPLITK6), 256, smemB>>>(
        p_yh, D_INNER, p_w6h, D_INNER, D_MODEL,
        p_part6, D_MODEL, nullptr, D_INNER / SPLITK6, (size_t)BL * D_MODEL);
    // 7) fused reduce + residual + LayerNorm -> out
    reduce_ln_kernel<<<BL, 256>>>(x, ln_w, ln_b, out);
}

// round 15
// speedup vs baseline: 1.1823x; 1.0433x over previous
#include <cuda_runtime.h>
#include <cuda_fp16.h>
#include <math.h>
#include <stdint.h>

#define D_MODEL 1024
#define D_INNER 2048
#define D_STATE 16
#define DT_RANK 64
#define NB 2
#define LSEQ 2048
#define BL (NB*LSEQ)            /* 4096 rows total */
#define XDBL_W 96
#define SPLITK 8
#define SPLITK6 2

// ---------------- scratch (device globals) ----------------
__device__ float  g_part[(size_t)SPLITK * BL * XDBL_W];    // GEMM3 split-K partials
__device__ float  g_part6[(size_t)SPLITK6 * BL * D_MODEL]; // GEMM6 split-K partials
// fp16 buffers (16B-aligned for cp.async)
__device__ __align__(16) __half g_xzh[(size_t)BL * 2 * D_INNER];
__device__ __align__(16) __half g_deltah[(size_t)BL * D_INNER];
__device__ __align__(16) __half g_uh[(size_t)BL * D_INNER];
__device__ __align__(16) __half g_xdbl_h[(size_t)BL * XDBL_W];  // [dt(64) | BC interleaved(32)]
__device__ __align__(16) __half g_yh[(size_t)BL * D_INNER];
__device__ __align__(16) __half g_xh[(size_t)BL * D_MODEL];
__device__ __align__(16) __half g_w1h[(size_t)2 * D_INNER * D_MODEL];
__device__ __align__(16) __half g_w3h[(size_t)XDBL_W * D_INNER];
__device__ __align__(16) __half g_w4h[(size_t)D_INNER * DT_RANK];
__device__ __align__(16) __half g_w6h[(size_t)D_MODEL * D_INNER];

__device__ __forceinline__ void mma_f16(float* d, const uint32_t* a, const uint32_t* b) {
    asm volatile(
        "mma.sync.aligned.m16n8k16.row.col.f32.f16.f16.f32 "
        "{%0,%1,%2,%3}, {%4,%5,%6,%7}, {%8,%9}, {%0,%1,%2,%3};"
        : "+f"(d[0]), "+f"(d[1]), "+f"(d[2]), "+f"(d[3])
        : "r"(a[0]), "r"(a[1]), "r"(a[2]), "r"(a[3]), "r"(b[0]), "r"(b[1]));
}
__device__ __forceinline__ void ldsm4(uint32_t* r, uint32_t addr) {
    asm volatile("ldmatrix.sync.aligned.m8n8.x4.shared.b16 {%0,%1,%2,%3}, [%4];"
                 : "=r"(r[0]), "=r"(r[1]), "=r"(r[2]), "=r"(r[3]) : "r"(addr));
}
__device__ __forceinline__ void cp16(uint32_t dst, const void* src, bool pred) {
    int sz = pred ? 16 : 0;
    asm volatile("cp.async.cg.shared.global [%0], [%1], 16, %2;"
                 :: "r"(dst), "l"(src), "r"(sz) : "memory");
}
#define CP_COMMIT() asm volatile("cp.async.commit_group;" ::: "memory")
#define CP_WAIT(n)  asm volatile("cp.async.wait_group %0;" :: "n"(n) : "memory")

// ================= fp16 mma.sync GEMM, cp.async depth-2 (R9/R13) =================
#define SPITCH_H 40
#define A_HALVES (128 * SPITCH_H)
#define STAGE_HALVES (2 * A_HALVES)
#define STAGEB (STAGE_HALVES * 2)
#define NSTAGE 4

template<int EPI, typename OutT>
__global__ __launch_bounds__(256, 2)
void gemm_h(const __half* __restrict__ A, int lda,
            const __half* __restrict__ Bw, int ldb, int Nact,
            OutT* __restrict__ C, int ldc,
            const float* __restrict__ aux, int K, size_t csplit)
{
    extern __shared__ __half smem[];
    const int tid = threadIdx.x;
    const int wid = tid >> 5;
    const int lane = tid & 31;
    const int g = lane >> 2;
    const int t4 = lane & 3;
    const int warp_m = wid >> 1;
    const int warp_n = wid & 1;
    const int bm = blockIdx.y * 128;
    const int bn = blockIdx.x * 128;

    const int kbase = blockIdx.z * K;
    C += (size_t)blockIdx.z * csplit;

    const int row = tid >> 1;
    const int seg = (tid & 1) << 4;

    const bool bok = (bn + row) < Nact;
    const __half* Ap = A + (size_t)(bm + row) * lda + kbase + seg;
    const __half* Bp = Bw + (size_t)(bn + row) * ldb + kbase + seg;

    uint32_t sbase;
    asm("{ .reg .u64 t; cvta.to.shared.u64 t, %1; cvt.u32.u64 %0, t; }"
        : "=r"(sbase) : "l"(smem));
    const uint32_t dA = sbase + ((uint32_t)row * SPITCH_H + seg) * 2;
    const uint32_t dB = dA + A_HALVES * 2;

    uint32_t aoff[2], boff[4];
#pragma unroll
    for (int mt = 0; mt < 2; mt++)
        aoff[mt] = (((uint32_t)(warp_m * 32 + mt * 16 + (lane & 15))) * SPITCH_H
                    + ((lane >> 4) << 3)) * 2;
#pragma unroll
    for (int nt2 = 0; nt2 < 4; nt2++)
        boff[nt2] = A_HALVES * 2 +
                    (((uint32_t)(warp_n * 64 + nt2 * 16 + (lane & 7) + ((lane >> 4) << 3)))
                     * SPITCH_H + (((lane >> 3) & 1) << 3)) * 2;

    float acc[2][8][4];
#pragma unroll
    for (int mt = 0; mt < 2; mt++)
#pragma unroll
        for (int nt = 0; nt < 8; nt++)
#pragma unroll
            for (int q = 0; q < 4; q++) acc[mt][nt][q] = 0.f;

    const int NC = K >> 5;

    auto issue = [&](int c) {
        const uint32_t so = (uint32_t)(c & (NSTAGE - 1)) * STAGEB;
        const int k0 = c << 5;
        cp16(dA + so,      Ap + k0,     true);
        cp16(dA + so + 16, Ap + k0 + 8, true);
        cp16(dB + so,      Bp + k0,     bok);
        cp16(dB + so + 16, Bp + k0 + 8, bok);
        CP_COMMIT();
    };
    auto compute = [&](int buf) {
        const uint32_t so = sbase + (uint32_t)buf * STAGEB;
#pragma unroll
        for (int ks = 0; ks < 2; ks++) {
            const uint32_t kb = so + ks * 32;
            uint32_t afr[2][4], bfr[4][4];
#pragma unroll
            for (int mt = 0; mt < 2; mt++) ldsm4(afr[mt], kb + aoff[mt]);
#pragma unroll
            for (int nt2 = 0; nt2 < 4; nt2++) ldsm4(bfr[nt2], kb + boff[nt2]);
#pragma unroll
            for (int mt = 0; mt < 2; mt++)
#pragma unroll
                for (int nt2 = 0; nt2 < 4; nt2++) {
                    mma_f16(acc[mt][nt2 * 2],     afr[mt], &bfr[nt2][0]);
                    mma_f16(acc[mt][nt2 * 2 + 1], afr[mt], &bfr[nt2][2]);
                }
        }
    };

    issue(0);
    if (NC > 1) issue(1);

    for (int c = 0; c < NC; c++) {
        if (c + 1 < NC) CP_WAIT(1);
        else            CP_WAIT(0);
        __syncthreads();
        if (c + 2 < NC) issue(c + 2);
        compute(c & (NSTAGE - 1));
    }

#pragma unroll
    for (int mt = 0; mt < 2; mt++) {
        const int r0 = bm + warp_m * 32 + mt * 16 + g;
#pragma unroll
        for (int nt = 0; nt < 8; nt++) {
            const int col = bn + warp_n * 64 + nt * 8 + 2 * t4;
            if (col >= Nact) continue;
#pragma unroll
            for (int hrow = 0; hrow < 2; hrow++) {
                const int r = r0 + hrow * 8;
                float2 v = make_float2(acc[mt][nt][hrow * 2], acc[mt][nt][hrow * 2 + 1]);
                if (EPI == 1) {
                    float2 bs = *(const float2*)(aux + col);
                    v.x += bs.x; v.y += bs.y;
                    v.x = fmaxf(v.x, 0.f) + log1pf(expf(-fabsf(v.x)));
                    v.y = fmaxf(v.y, 0.f) + log1pf(expf(-fabsf(v.y)));
                }
                if (sizeof(OutT) == 2) {
                    *(__half2*)((__half*)C + (size_t)r * ldc + col) = __float22half2_rn(v);
                } else {
                    *(float2*)((float*)C + (size_t)r * ldc + col) = v;
                }
            }
        }
    }
}

// ---------------- fp32 -> fp16 conversion ----------------
__global__ __launch_bounds__(256)
void tohalf_kernel(const float* __restrict__ src, __half* __restrict__ dst, int n4)
{
    int i = blockIdx.x * blockDim.x + threadIdx.x;
    if (i >= n4) return;
    float4 v = ((const float4*)src)[i];
    ((__half2*)dst)[i * 2]     = __floats2half2_rn(v.x, v.y);
    ((__half2*)dst)[i * 2 + 1] = __floats2half2_rn(v.z, v.w);
}

// ---------------- fused cvt of 3 weight buffers ----------------
__global__ __launch_bounds__(256)
void tohalf3_kernel(const float* __restrict__ s0, __half* __restrict__ d0, int n0_4,
                    const float* __restrict__ s1, __half* __restrict__ d1, int n1_4,
                    const float* __restrict__ s2, __half* __restrict__ d2, int n2_4)
{
    int i = blockIdx.x * blockDim.x + threadIdx.x;
    const float* s; __half* d; int j;
    if (i < n0_4)                { s = s0; d = d0; j = i; }
    else if (i < n0_4 + n1_4)    { s = s1; d = d1; j = i - n0_4; }
    else if (i < n0_4 + n1_4 + n2_4) { s = s2; d = d2; j = i - n0_4 - n1_4; }
    else return;
    float4 v = ((const float4*)s)[j];
    ((__half2*)d)[j * 2]     = __floats2half2_rn(v.x, v.y);
    ((__half2*)d)[j * 2 + 1] = __floats2half2_rn(v.z, v.w);
}

// ---------------- split-K reduce -> half xdbl with BC interleave ----------------
__global__ __launch_bounds__(256)
void reduce_split_kernel()
{
    int idx = blockIdx.x * blockDim.x + threadIdx.x;
    if (idx >= BL * XDBL_W) return;
    float s = 0.f;
#pragma unroll
    for (int k = 0; k < SPLITK; k++)
        s += g_part[(size_t)k * BL * XDBL_W + idx];
    int row = idx / XDBL_W;
    int c = idx - row * XDBL_W;
    int oc;
    if (c < DT_RANK) {
        oc = c;
    } else if (c < DT_RANK + D_STATE) {
        int nb = c - DT_RANK;
        oc = DT_RANK + (nb >> 1) * 4 + (nb & 1);
    } else {
        int nc = c - DT_RANK - D_STATE;
        oc = DT_RANK + (nc >> 1) * 4 + 2 + (nc & 1);
    }
    g_xdbl_h[(size_t)row * XDBL_W + oc] = __float2half_rn(s);
}

// ---------------- causal depthwise conv + bias + SiLU (half2, 2 ch/thread) ----------------
__global__ __launch_bounds__(256)
void conv_silu_kernel(const float* __restrict__ cw, const float* __restrict__ cb)
{
    int idx = blockIdx.x * blockDim.x + threadIdx.x;
    if (idx >= BL * D_INNER / 2) return;
    int dp = idx & (D_INNER / 2 - 1);
    int d = dp << 1;
    int row = idx >> 10;
    int l = row & (LSEQ - 1);

    float4 wa = *(const float4*)(cw + d * 4);
    float4 wb = *(const float4*)(cw + d * 4 + 4);
    float2 bias = *(const float2*)(cb + d);
    float a0 = bias.x, a1 = bias.y;

    const __half2* src = (const __half2*)g_xzh + dp;
#pragma unroll
    for (int j = 0; j < 4; j++) {
        int lj = l - 3 + j;
        if (lj >= 0) {
            float2 v = __half22float2(src[(size_t)(row - 3 + j) * 2048]);
            float w0 = (j == 0) ? wa.x : (j == 1) ? wa.y : (j == 2) ? wa.z : wa.w;
            float w1 = (j == 0) ? wb.x : (j == 1) ? wb.y : (j == 2) ? wb.z : wb.w;
            a0 = fmaf(v.x, w0, a0);
            a1 = fmaf(v.y, w1, a1);
        }
    }
    float s0 = a0 / (1.f + __expf(-a0));
    float s1 = a1 / (1.f + __expf(-a1));
    ((__half2*)g_uh)[idx] = __floats2half2_rn(s0, s1);
}

// ---------------- selective scan: 8 lanes/channel, 2 states/lane ----------------
// Ping-pong unrolled x2 over 16 steps: NO register copies between buffers.
__global__ __launch_bounds__(128)
void scan_kernel(const float* __restrict__ A_log, const float* __restrict__ Dp)
{
    const int tid = threadIdx.x;
    const int ch = blockIdx.x * 16 + (tid >> 3);
    const int b = ch >> 11;
    const int d = ch & (D_INNER - 1);
    const int ls = tid & 7;
    const int n0 = ls << 1;

    const float A0 = -expf(A_log[d * D_STATE + n0]);
    const float A1 = -expf(A_log[d * D_STATE + n0 + 1]);
    const float Dd = Dp[d];

    float h0 = 0.f, h1 = 0.f;
    const __half* xd = g_xdbl_h + (size_t)b * LSEQ * XDBL_W + DT_RANK + ls * 4;
    const size_t base2 = (size_t)b * LSEQ * D_INNER + d;
    const size_t basez = (size_t)b * LSEQ * (2 * D_INNER) + D_INNER + d;

    auto load_group = [&](int l, float* D_, float* U_, float* Z_, float2* B_, float2* C_) {
#pragma unroll
        for (int j = 0; j < 4; j++) {
            size_t o2 = base2 + (size_t)(l + j) * D_INNER;
            D_[j] = __half2float(g_deltah[o2]);
            U_[j] = __half2float(g_uh[o2]);
        }
        if (ls == 0) {
#pragma unroll
            for (int j = 0; j < 4; j++)
                Z_[j] = __half2float(g_xzh[basez + (size_t)(l + j) * (2 * D_INNER)]);
        }
#pragma unroll
        for (int j = 0; j < 4; j++) {
            uint2 bc = *(const uint2*)(xd + (size_t)(l + j) * XDBL_W);
            B_[j] = __half22float2(*(const __half2*)&bc.x);
            C_[j] = __half22float2(*(const __half2*)&bc.y);
        }
    };

    auto proc = [&](int l0, const float* D_, const float* U_, const float* Z_,
                    const float2* B_, const float2* C_) {
        float yp[4];
#pragma unroll
        for (int j = 0; j < 4; j++) {
            float e0 = __expf(D_[j] * A0);
            float e1 = __expf(D_[j] * A1);
            float du = D_[j] * U_[j];
            h0 = fmaf(e0, h0, du * B_[j].x);
            h1 = fmaf(e1, h1, du * B_[j].y);
            yp[j] = fmaf(h0, C_[j].x, h1 * C_[j].y);
        }
#pragma unroll
        for (int j = 0; j < 4; j++) yp[j] += __shfl_xor_sync(0xffffffffu, yp[j], 1);
#pragma unroll
        for (int j = 0; j < 4; j++) yp[j] += __shfl_xor_sync(0xffffffffu, yp[j], 2);
#pragma unroll
        for (int j = 0; j < 4; j++) yp[j] += __shfl_xor_sync(0xffffffffu, yp[j], 4);
        if (ls == 0) {
#pragma unroll
            for (int j = 0; j < 4; j++) {
                float z = Z_[j];
                float sz = z / (1.f + __expf(-z));
                g_yh[base2 + (size_t)(l0 + j) * D_INNER] =
                    __float2half_rn(fmaf(U_[j], Dd, yp[j]) * sz);
            }
        }
    };

    float aD[4], aU[4], aZ[4]; float2 aB[4], aC[4];
    float bD[4], bU[4], bZ[4]; float2 bB[4], bC[4];
    float tD[4], tU[4], tZ[4]; float2 tB[4], tC[4];
    float sD[4], sU[4], sZ[4]; float2 sB[4], sC[4];

    load_group(0, aD, aU, aZ, aB, aC);
    load_group(4, bD, bU, bZ, bB, bC);

    // ping-pong over 16 steps: process (a,b) while loading (t,s), then swap roles.
    for (int l0 = 0; l0 < LSEQ; l0 += 16) {
        if (l0 + 8  < LSEQ) load_group(l0 + 8,  tD, tU, tZ, tB, tC);
        if (l0 + 12 < LSEQ) load_group(l0 + 12, sD, sU, sZ, sB, sC);
        proc(l0,     aD, aU, aZ, aB, aC);
        proc(l0 + 4, bD, bU, bZ, bB, bC);
        if (l0 + 16 < LSEQ) {
            load_group(l0 + 16, aD, aU, aZ, aB, aC);
            load_group(l0 + 20, bD, bU, bZ, bB, bC);
        }
        proc(l0 + 8,  tD, tU, tZ, tB, tC);
        proc(l0 + 12, sD, sU, sZ, sB, sC);
    }
}

// ---------------- fused GEMM6-reduce + residual + LayerNorm ----------------
__global__ __launch_bounds__(256)
void reduce_ln_kernel(const float* __restrict__ x,
                      const float* __restrict__ lnw, const float* __restrict__ lnb,
                      float* __restrict__ out)
{
    int row = blockIdx.x;
    int tid = threadIdx.x;
    const float* p0 = g_part6 + (size_t)row * D_MODEL;
    const float* p1 = g_part6 + (size_t)BL * D_MODEL + (size_t)row * D_MODEL;
    const float* xr = x + (size_t)row * D_MODEL;

    float v[4];
    float s = 0.f, sq = 0.f;
#pragma unroll
    for (int i = 0; i < 4; i++) {
        int c = tid + i * 256;
        v[i] = p0[c] + p1[c] + xr[c];
        s += v[i];
        sq += v[i] * v[i];
    }
#pragma unroll
    for (int off = 16; off; off >>= 1) {
        s += __shfl_xor_sync(0xffffffffu, s, off);
        sq += __shfl_xor_sync(0xffffffffu, sq, off);
    }
    __shared__ float ss[8], ssq[8];
    __shared__ float mu_s, rs_s;
    if ((tid & 31) == 0) { ss[tid >> 5] = s; ssq[tid >> 5] = sq; }
    __syncthreads();
    if (tid == 0) {
        float S = 0.f, SQ = 0.f;
#pragma unroll
        for (int i = 0; i < 8; i++) { S += ss[i]; SQ += ssq[i]; }
        float mu = S * (1.f / D_MODEL);
        float var = SQ * (1.f / D_MODEL) - mu * mu;
        mu_s = mu;
        rs_s = rsqrtf(var + 1e-5f);
    }
    __syncthreads();
    float mu = mu_s, rs = rs_s;
#pragma unroll
    for (int i = 0; i < 4; i++) {
        int c = tid + i * 256;
        out[(size_t)row * D_MODEL + c] = (v[i] - mu) * rs * lnw[c] + lnb[c];
    }
}

// ---------------- host launch ----------------
extern "C" void kernel_launch(void* const* d_in, const int* in_sizes, int n_in,
                              void* d_out, int out_size)
{
    const float* x          = (const float*)d_in[0];
    const float* in_proj_w  = (const float*)d_in[1];
    const float* conv_w     = (const float*)d_in[2];
    const float* conv_b     = (const float*)d_in[3];
    const float* x_proj_w   = (const float*)d_in[4];
    const float* dt_proj_w  = (const float*)d_in[5];
    const float* dt_proj_b  = (const float*)d_in[6];
    const float* A_log      = (const float*)d_in[7];
    const float* Dp         = (const float*)d_in[8];
    const float* out_proj_w = (const float*)d_in[9];
    const float* ln_w       = (const float*)d_in[10];
    const float* ln_b       = (const float*)d_in[11];
    float* out = (float*)d_out;

    float *p_part, *p_part6;
    __half *p_xzh, *p_deltah, *p_uh, *p_xdblh, *p_yh, *p_xh;
    __half *p_w1h, *p_w3h, *p_w4h, *p_w6h;
    cudaGetSymbolAddress((void**)&p_part,   g_part);
    cudaGetSymbolAddress((void**)&p_part6,  g_part6);
    cudaGetSymbolAddress((void**)&p_xzh,    g_xzh);
    cudaGetSymbolAddress((void**)&p_deltah, g_deltah);
    cudaGetSymbolAddress((void**)&p_uh,     g_uh);
    cudaGetSymbolAddress((void**)&p_xdblh,  g_xdbl_h);
    cudaGetSymbolAddress((void**)&p_yh,     g_yh);
    cudaGetSymbolAddress((void**)&p_xh,     g_xh);
    cudaGetSymbolAddress((void**)&p_w1h,    g_w1h);
    cudaGetSymbolAddress((void**)&p_w3h,    g_w3h);
    cudaGetSymbolAddress((void**)&p_w4h,    g_w4h);
    cudaGetSymbolAddress((void**)&p_w6h,    g_w6h);

    const int smemB = NSTAGE * STAGEB;   // 81920
    cudaFuncSetAttribute((const void*)gemm_h<0, __half>, cudaFuncAttributeMaxDynamicSharedMemorySize, smemB);
    cudaFuncSetAttribute((const void*)gemm_h<0, float>,  cudaFuncAttributeMaxDynamicSharedMemorySize, smemB);
    cudaFuncSetAttribute((const void*)gemm_h<1, __half>, cudaFuncAttributeMaxDynamicSharedMemorySize, smemB);

    // launch 0: cvt x; 1: cvt w1; 2: fused cvt w3/w4/w6
    {
        int nx4 = (BL * D_MODEL) / 4;
        tohalf_kernel<<<(nx4 + 255) / 256, 256>>>(x, p_xh, nx4);
        int nw1_4 = (2 * D_INNER * D_MODEL) / 4;
        tohalf_kernel<<<(nw1_4 + 255) / 256, 256>>>(in_proj_w, p_w1h, nw1_4);
        int n3 = (XDBL_W * D_INNER) / 4;
        int n4 = (D_INNER * DT_RANK) / 4;
        int n6 = (D_MODEL * D_INNER) / 4;
        tohalf3_kernel<<<(n3 + n4 + n6 + 255) / 256, 256>>>(
            x_proj_w, p_w3h, n3, dt_proj_w, p_w4h, n4, out_proj_w, p_w6h, n6);
    }

    // 1) xz = x @ in_proj_w^T [4096,4096] K=1024 -> half  (launch 3 = profiled control)
    gemm_h<0, __half><<<dim3(32, 32), 256, smemB>>>(
        p_xh, D_MODEL, p_w1h, D_MODEL, 2 * D_INNER,
        p_xzh, 2 * D_INNER, nullptr, D_MODEL, 0);

    // 2) u = silu(causal_conv(xi) + cb) -> half
    conv_silu_kernel<<<(BL * D_INNER / 2 + 255) / 256, 256>>>(conv_w, conv_b);
    // 3) x_dbl = u @ x_proj_w^T [4096,96], split-K x8 + reduce (BC interleave) -> half
    gemm_h<0, float><<<dim3(1, 32, SPLITK), 256, smemB>>>(
        p_uh, D_INNER, p_w3h, D_INNER, XDBL_W,
        p_part, XDBL_W, nullptr, D_INNER / SPLITK, (size_t)BL * XDBL_W);
    reduce_split_kernel<<<(BL * XDBL_W + 255) / 256, 256>>>();
    // 4) delta = softplus(dt @ dt_proj_w^T + b) [4096,2048] K=64 -> half
    gemm_h<1, __half><<<dim3(16, 32), 256, smemB>>>(
        p_xdblh, XDBL_W, p_w4h, DT_RANK, D_INNER,
        p_deltah, D_INNER, dt_proj_b, DT_RANK, 0);
    // 5) selective scan + skip + gate -> half y (ping-pong, copy-free)
    scan_kernel<<<256, 128>>>(A_log, Dp);
    // 6) h-partials = y @ out_proj_w^T, split-K x2 [4096,1024]
    gemm_h<0, float><<<dim3(8, 32, SPLITK6), 256, smemB>>>(
        p_yh, D_INNER, p_w6h, D_INNER, D_MODEL,
        p_part6, D_MODEL, nullptr, D_INNER / SPLITK6, (size_t)BL * D_MODEL);
    // 7) fused reduce + residual + LayerNorm -> out
    reduce_ln_kernel<<<BL, 256>>>(x, ln_w, ln_b, out);
}

// round 16
// speedup vs baseline: 1.2506x; 1.0578x over previous
#include <cuda_runtime.h>
#include <cuda_fp16.h>
#include <math.h>
#include <stdint.h>

#define D_MODEL 1024
#define D_INNER 2048
#define D_STATE 16
#define DT_RANK 64
#define NB 2
#define LSEQ 2048
#define BL (NB*LSEQ)            /* 4096 rows total */
#define XDBL_W 96
#define SPLITK 8
#define SPLITK6 2

// ---------------- scratch (device globals) ----------------
__device__ float  g_part[(size_t)SPLITK * BL * XDBL_W];    // GEMM3 split-K partials
__device__ float  g_part6[(size_t)SPLITK6 * BL * D_MODEL]; // GEMM6 split-K partials
// fp16 buffers (16B-aligned for cp.async)
__device__ __align__(16) __half  g_xzh[(size_t)BL * 2 * D_INNER];
__device__ __align__(16) __half2 g_du[(size_t)BL * D_INNER];    // packed (delta, u)
__device__ __align__(16) __half  g_uh[(size_t)BL * D_INNER];
__device__ __align__(16) __half  g_xdbl_h[(size_t)BL * XDBL_W]; // [dt(64)|BC interleaved(32)]
__device__ __align__(16) __half  g_yh[(size_t)BL * D_INNER];
__device__ __align__(16) __half  g_xh[(size_t)BL * D_MODEL];
__device__ __align__(16) __half  g_w1h[(size_t)2 * D_INNER * D_MODEL];
__device__ __align__(16) __half  g_w3h[(size_t)XDBL_W * D_INNER];
__device__ __align__(16) __half  g_w4h[(size_t)D_INNER * DT_RANK];
__device__ __align__(16) __half  g_w6h[(size_t)D_MODEL * D_INNER];

__device__ __forceinline__ void mma_f16(float* d, const uint32_t* a, const uint32_t* b) {
    asm volatile(
        "mma.sync.aligned.m16n8k16.row.col.f32.f16.f16.f32 "
        "{%0,%1,%2,%3}, {%4,%5,%6,%7}, {%8,%9}, {%0,%1,%2,%3};"
        : "+f"(d[0]), "+f"(d[1]), "+f"(d[2]), "+f"(d[3])
        : "r"(a[0]), "r"(a[1]), "r"(a[2]), "r"(a[3]), "r"(b[0]), "r"(b[1]));
}
__device__ __forceinline__ void ldsm4(uint32_t* r, uint32_t addr) {
    asm volatile("ldmatrix.sync.aligned.m8n8.x4.shared.b16 {%0,%1,%2,%3}, [%4];"
                 : "=r"(r[0]), "=r"(r[1]), "=r"(r[2]), "=r"(r[3]) : "r"(addr));
}
__device__ __forceinline__ void cp16(uint32_t dst, const void* src, bool pred) {
    int sz = pred ? 16 : 0;
    asm volatile("cp.async.cg.shared.global [%0], [%1], 16, %2;"
                 :: "r"(dst), "l"(src), "r"(sz) : "memory");
}
#define CP_COMMIT() asm volatile("cp.async.commit_group;" ::: "memory")
#define CP_WAIT(n)  asm volatile("cp.async.wait_group %0;" :: "n"(n) : "memory")

// ================= fp16 mma.sync GEMM, cp.async depth-2 =================
// EPI: 0 plain, 1 softplus+pack(delta,u)->g_du
#define SPITCH_H 40
#define A_HALVES (128 * SPITCH_H)
#define STAGE_HALVES (2 * A_HALVES)
#define STAGEB (STAGE_HALVES * 2)
#define NSTAGE 4

template<int EPI, typename OutT>
__global__ __launch_bounds__(256, 2)
void gemm_h(const __half* __restrict__ A, int lda,
            const __half* __restrict__ Bw, int ldb, int Nact,
            OutT* __restrict__ C, int ldc,
            const float* __restrict__ aux, int K, size_t csplit)
{
    extern __shared__ __half smem[];
    const int tid = threadIdx.x;
    const int wid = tid >> 5;
    const int lane = tid & 31;
    const int g = lane >> 2;
    const int t4 = lane & 3;
    const int warp_m = wid >> 1;
    const int warp_n = wid & 1;
    const int bm = blockIdx.y * 128;
    const int bn = blockIdx.x * 128;

    const int kbase = blockIdx.z * K;
    C += (size_t)blockIdx.z * csplit;

    const int row = tid >> 1;
    const int seg = (tid & 1) << 4;

    const bool bok = (bn + row) < Nact;
    const __half* Ap = A + (size_t)(bm + row) * lda + kbase + seg;
    const __half* Bp = Bw + (size_t)(bn + row) * ldb + kbase + seg;

    uint32_t sbase;
    asm("{ .reg .u64 t; cvta.to.shared.u64 t, %1; cvt.u32.u64 %0, t; }"
        : "=r"(sbase) : "l"(smem));
    const uint32_t dA = sbase + ((uint32_t)row * SPITCH_H + seg) * 2;
    const uint32_t dB = dA + A_HALVES * 2;

    uint32_t aoff[2], boff[4];
#pragma unroll
    for (int mt = 0; mt < 2; mt++)
        aoff[mt] = (((uint32_t)(warp_m * 32 + mt * 16 + (lane & 15))) * SPITCH_H
                    + ((lane >> 4) << 3)) * 2;
#pragma unroll
    for (int nt2 = 0; nt2 < 4; nt2++)
        boff[nt2] = A_HALVES * 2 +
                    (((uint32_t)(warp_n * 64 + nt2 * 16 + (lane & 7) + ((lane >> 4) << 3)))
                     * SPITCH_H + (((lane >> 3) & 1) << 3)) * 2;

    float acc[2][8][4];
#pragma unroll
    for (int mt = 0; mt < 2; mt++)
#pragma unroll
        for (int nt = 0; nt < 8; nt++)
#pragma unroll
            for (int q = 0; q < 4; q++) acc[mt][nt][q] = 0.f;

    const int NC = K >> 5;

    auto issue = [&](int c) {
        const uint32_t so = (uint32_t)(c & (NSTAGE - 1)) * STAGEB;
        const int k0 = c << 5;
        cp16(dA + so,      Ap + k0,     true);
        cp16(dA + so + 16, Ap + k0 + 8, true);
        cp16(dB + so,      Bp + k0,     bok);
        cp16(dB + so + 16, Bp + k0 + 8, bok);
        CP_COMMIT();
    };
    auto compute = [&](int buf) {
        const uint32_t so = sbase + (uint32_t)buf * STAGEB;
#pragma unroll
        for (int ks = 0; ks < 2; ks++) {
            const uint32_t kb = so + ks * 32;
            uint32_t afr[2][4], bfr[4][4];
#pragma unroll
            for (int mt = 0; mt < 2; mt++) ldsm4(afr[mt], kb + aoff[mt]);
#pragma unroll
            for (int nt2 = 0; nt2 < 4; nt2++) ldsm4(bfr[nt2], kb + boff[nt2]);
#pragma unroll
            for (int mt = 0; mt < 2; mt++)
#pragma unroll
                for (int nt2 = 0; nt2 < 4; nt2++) {
                    mma_f16(acc[mt][nt2 * 2],     afr[mt], &bfr[nt2][0]);
                    mma_f16(acc[mt][nt2 * 2 + 1], afr[mt], &bfr[nt2][2]);
                }
        }
    };

    issue(0);
    if (NC > 1) issue(1);

    for (int c = 0; c < NC; c++) {
        if (c + 1 < NC) CP_WAIT(1);
        else            CP_WAIT(0);
        __syncthreads();
        if (c + 2 < NC) issue(c + 2);
        compute(c & (NSTAGE - 1));
    }

#pragma unroll
    for (int mt = 0; mt < 2; mt++) {
        const int r0 = bm + warp_m * 32 + mt * 16 + g;
#pragma unroll
        for (int nt = 0; nt < 8; nt++) {
            const int col = bn + warp_n * 64 + nt * 8 + 2 * t4;
            if (col >= Nact) continue;
#pragma unroll
            for (int hrow = 0; hrow < 2; hrow++) {
                const int r = r0 + hrow * 8;
                float2 v = make_float2(acc[mt][nt][hrow * 2], acc[mt][nt][hrow * 2 + 1]);
                if (EPI == 1) {
                    float2 bs = *(const float2*)(aux + col);
                    v.x += bs.x; v.y += bs.y;
                    v.x = fmaxf(v.x, 0.f) + log1pf(expf(-fabsf(v.x)));
                    v.y = fmaxf(v.y, 0.f) + log1pf(expf(-fabsf(v.y)));
                    // pack (delta, u) interleaved
                    __half2 uv = *(const __half2*)(g_uh + (size_t)r * ldc + col);
                    __half2 dd = __floats2half2_rn(v.x, v.y);
                    g_du[(size_t)r * ldc + col]     = __halves2half2(__low2half(dd),  __low2half(uv));
                    g_du[(size_t)r * ldc + col + 1] = __halves2half2(__high2half(dd), __high2half(uv));
                } else {
                    if (sizeof(OutT) == 2) {
                        *(__half2*)((__half*)C + (size_t)r * ldc + col) = __float22half2_rn(v);
                    } else {
                        *(float2*)((float*)C + (size_t)r * ldc + col) = v;
                    }
                }
            }
        }
    }
}

// ---------------- fp32 -> fp16 conversion ----------------
__global__ __launch_bounds__(256)
void tohalf_kernel(const float* __restrict__ src, __half* __restrict__ dst, int n4)
{
    int i = blockIdx.x * blockDim.x + threadIdx.x;
    if (i >= n4) return;
    float4 v = ((const float4*)src)[i];
    ((__half2*)dst)[i * 2]     = __floats2half2_rn(v.x, v.y);
    ((__half2*)dst)[i * 2 + 1] = __floats2half2_rn(v.z, v.w);
}

// ---------------- fused cvt of 3 weight buffers ----------------
__global__ __launch_bounds__(256)
void tohalf3_kernel(const float* __restrict__ s0, __half* __restrict__ d0, int n0_4,
                    const float* __restrict__ s1, __half* __restrict__ d1, int n1_4,
                    const float* __restrict__ s2, __half* __restrict__ d2, int n2_4)
{
    int i = blockIdx.x * blockDim.x + threadIdx.x;
    const float* s; __half* d; int j;
    if (i < n0_4)                { s = s0; d = d0; j = i; }
    else if (i < n0_4 + n1_4)    { s = s1; d = d1; j = i - n0_4; }
    else if (i < n0_4 + n1_4 + n2_4) { s = s2; d = d2; j = i - n0_4 - n1_4; }
    else return;
    float4 v = ((const float4*)s)[j];
    ((__half2*)d)[j * 2]     = __floats2half2_rn(v.x, v.y);
    ((__half2*)d)[j * 2 + 1] = __floats2half2_rn(v.z, v.w);
}

// ---------------- split-K reduce -> half xdbl with BC interleave ----------------
__global__ __launch_bounds__(256)
void reduce_split_kernel()
{
    int idx = blockIdx.x * blockDim.x + threadIdx.x;
    if (idx >= BL * XDBL_W) return;
    float s = 0.f;
#pragma unroll
    for (int k = 0; k < SPLITK; k++)
        s += g_part[(size_t)k * BL * XDBL_W + idx];
    int row = idx / XDBL_W;
    int c = idx - row * XDBL_W;
    int oc;
    if (c < DT_RANK) {
        oc = c;
    } else if (c < DT_RANK + D_STATE) {
        int nb = c - DT_RANK;
        oc = DT_RANK + (nb >> 1) * 4 + (nb & 1);
    } else {
        int nc = c - DT_RANK - D_STATE;
        oc = DT_RANK + (nc >> 1) * 4 + 2 + (nc & 1);
    }
    g_xdbl_h[(size_t)row * XDBL_W + oc] = __float2half_rn(s);
}

// ---------------- causal depthwise conv + bias + SiLU (half2, 2 ch/thread) ----------------
__global__ __launch_bounds__(256)
void conv_silu_kernel(const float* __restrict__ cw, const float* __restrict__ cb)
{
    int idx = blockIdx.x * blockDim.x + threadIdx.x;
    if (idx >= BL * D_INNER / 2) return;
    int dp = idx & (D_INNER / 2 - 1);
    int d = dp << 1;
    int row = idx >> 10;
    int l = row & (LSEQ - 1);

    float4 wa = *(const float4*)(cw + d * 4);
    float4 wb = *(const float4*)(cw + d * 4 + 4);
    float2 bias = *(const float2*)(cb + d);
    float a0 = bias.x, a1 = bias.y;

    const __half2* src = (const __half2*)g_xzh + dp;
#pragma unroll
    for (int j = 0; j < 4; j++) {
        int lj = l - 3 + j;
        if (lj >= 0) {
            float2 v = __half22float2(src[(size_t)(row - 3 + j) * 2048]);
            float w0 = (j == 0) ? wa.x : (j == 1) ? wa.y : (j == 2) ? wa.z : wa.w;
            float w1 = (j == 0) ? wb.x : (j == 1) ? wb.y : (j == 2) ? wb.z : wb.w;
            a0 = fmaf(v.x, w0, a0);
            a1 = fmaf(v.y, w1, a1);
        }
    }
    float s0 = a0 / (1.f + __expf(-a0));
    float s1 = a1 / (1.f + __expf(-a1));
    ((__half2*)g_uh)[idx] = __floats2half2_rn(s0, s1);
}

// ---------------- selective scan: 8 lanes/channel, 2 states/lane ----------------
// 148 blocks x 224 threads (28 ch/block) = single balanced wave.
// Packed (delta,u) load; ping-pong, copy-free.
__global__ __launch_bounds__(224)
void scan_kernel(const float* __restrict__ A_log, const float* __restrict__ Dp)
{
    const int tid = threadIdx.x;
    const int ch_raw = blockIdx.x * 28 + (tid >> 3);
    const bool active = ch_raw < BL;
    const int ch = active ? ch_raw : (BL - 1);
    const int b = ch >> 11;
    const int d = ch & (D_INNER - 1);
    const int ls = tid & 7;
    const int n0 = ls << 1;

    const float A0 = -expf(A_log[d * D_STATE + n0]);
    const float A1 = -expf(A_log[d * D_STATE + n0 + 1]);
    const float Dd = Dp[d];

    float h0 = 0.f, h1 = 0.f;
    const __half* xd = g_xdbl_h + (size_t)b * LSEQ * XDBL_W + DT_RANK + ls * 4;
    const size_t base2 = (size_t)b * LSEQ * D_INNER + d;
    const size_t basez = (size_t)b * LSEQ * (2 * D_INNER) + D_INNER + d;

    auto load_group = [&](int l, float* D_, float* U_, float* Z_, float2* B_, float2* C_) {
#pragma unroll
        for (int j = 0; j < 4; j++) {
            __half2 du = g_du[base2 + (size_t)(l + j) * D_INNER];
            float2 f = __half22float2(du);
            D_[j] = f.x;
            U_[j] = f.y;
        }
        if (ls == 0) {
#pragma unroll
            for (int j = 0; j < 4; j++)
                Z_[j] = __half2float(g_xzh[basez + (size_t)(l + j) * (2 * D_INNER)]);
        }
#pragma unroll
        for (int j = 0; j < 4; j++) {
            uint2 bc = *(const uint2*)(xd + (size_t)(l + j) * XDBL_W);
            B_[j] = __half22float2(*(const __half2*)&bc.x);
            C_[j] = __half22float2(*(const __half2*)&bc.y);
        }
    };

    auto proc = [&](int l0, const float* D_, const float* U_, const float* Z_,
                    const float2* B_, const float2* C_) {
        float yp[4];
#pragma unroll
        for (int j = 0; j < 4; j++) {
            float e0 = __expf(D_[j] * A0);
            float e1 = __expf(D_[j] * A1);
            float du = D_[j] * U_[j];
            h0 = fmaf(e0, h0, du * B_[j].x);
            h1 = fmaf(e1, h1, du * B_[j].y);
            yp[j] = fmaf(h0, C_[j].x, h1 * C_[j].y);
        }
#pragma unroll
        for (int j = 0; j < 4; j++) yp[j] += __shfl_xor_sync(0xffffffffu, yp[j], 1);
#pragma unroll
        for (int j = 0; j < 4; j++) yp[j] += __shfl_xor_sync(0xffffffffu, yp[j], 2);
#pragma unroll
        for (int j = 0; j < 4; j++) yp[j] += __shfl_xor_sync(0xffffffffu, yp[j], 4);
        if (ls == 0 && active) {
#pragma unroll
            for (int j = 0; j < 4; j++) {
                float z = Z_[j];
                float sz = z / (1.f + __expf(-z));
                g_yh[base2 + (size_t)(l0 + j) * D_INNER] =
                    __float2half_rn(fmaf(U_[j], Dd, yp[j]) * sz);
            }
        }
    };

    float aD[4], aU[4], aZ[4]; float2 aB[4], aC[4];
    float bD[4], bU[4], bZ[4]; float2 bB[4], bC[4];
    float tD[4], tU[4], tZ[4]; float2 tB[4], tC[4];
    float sD[4], sU[4], sZ[4]; float2 sB[4], sC[4];

    load_group(0, aD, aU, aZ, aB, aC);
    load_group(4, bD, bU, bZ, bB, bC);

    for (int l0 = 0; l0 < LSEQ; l0 += 16) {
        if (l0 + 8  < LSEQ) load_group(l0 + 8,  tD, tU, tZ, tB, tC);
        if (l0 + 12 < LSEQ) load_group(l0 + 12, sD, sU, sZ, sB, sC);
        proc(l0,     aD, aU, aZ, aB, aC);
        proc(l0 + 4, bD, bU, bZ, bB, bC);
        if (l0 + 16 < LSEQ) {
            load_group(l0 + 16, aD, aU, aZ, aB, aC);
            load_group(l0 + 20, bD, bU, bZ, bB, bC);
        }
        proc(l0 + 8,  tD, tU, tZ, tB, tC);
        proc(l0 + 12, sD, sU, sZ, sB, sC);
    }
}

// ---------------- fused GEMM6-reduce + residual + LayerNorm ----------------
__global__ __launch_bounds__(256)
void reduce_ln_kernel(const float* __restrict__ x,
                      const float* __restrict__ lnw, const float* __restrict__ lnb,
                      float* __restrict__ out)
{
    int row = blockIdx.x;
    int tid = threadIdx.x;
    const float* p0 = g_part6 + (size_t)row * D_MODEL;
    const float* p1 = g_part6 + (size_t)BL * D_MODEL + (size_t)row * D_MODEL;
    const float* xr = x + (size_t)row * D_MODEL;

    float v[4];
    float s = 0.f, sq = 0.f;
#pragma unroll
    for (int i = 0; i < 4; i++) {
        int c = tid + i * 256;
        v[i] = p0[c] + p1[c] + xr[c];
        s += v[i];
        sq += v[i] * v[i];
    }
#pragma unroll
    for (int off = 16; off; off >>= 1) {
        s += __shfl_xor_sync(0xffffffffu, s, off);
        sq += __shfl_xor_sync(0xffffffffu, sq, off);
    }
    __shared__ float ss[8], ssq[8];
    __shared__ float mu_s, rs_s;
    if ((tid & 31) == 0) { ss[tid >> 5] = s; ssq[tid >> 5] = sq; }
    __syncthreads();
    if (tid == 0) {
        float S = 0.f, SQ = 0.f;
#pragma unroll
        for (int i = 0; i < 8; i++) { S += ss[i]; SQ += ssq[i]; }
        float mu = S * (1.f / D_MODEL);
        float var = SQ * (1.f / D_MODEL) - mu * mu;
        mu_s = mu;
        rs_s = rsqrtf(var + 1e-5f);
    }
    __syncthreads();
    float mu = mu_s, rs = rs_s;
#pragma unroll
    for (int i = 0; i < 4; i++) {
        int c = tid + i * 256;
        out[(size_t)row * D_MODEL + c] = (v[i] - mu) * rs * lnw[c] + lnb[c];
    }
}

// ---------------- host launch ----------------
extern "C" void kernel_launch(void* const* d_in, const int* in_sizes, int n_in,
                              void* d_out, int out_size)
{
    const float* x          = (const float*)d_in[0];
    const float* in_proj_w  = (const float*)d_in[1];
    const float* conv_w     = (const float*)d_in[2];
    const float* conv_b     = (const float*)d_in[3];
    const float* x_proj_w   = (const float*)d_in[4];
    const float* dt_proj_w  = (const float*)d_in[5];
    const float* dt_proj_b  = (const float*)d_in[6];
    const float* A_log      = (const float*)d_in[7];
    const float* Dp         = (const float*)d_in[8];
    const float* out_proj_w = (const float*)d_in[9];
    const float* ln_w       = (const float*)d_in[10];
    const float* ln_b       = (const float*)d_in[11];
    float* out = (float*)d_out;

    float *p_part, *p_part6;
    __half *p_xzh, *p_uh, *p_xdblh, *p_yh, *p_xh;
    __half *p_w1h, *p_w3h, *p_w4h, *p_w6h;
    __half2 *p_du;
    cudaGetSymbolAddress((void**)&p_part,   g_part);
    cudaGetSymbolAddress((void**)&p_part6,  g_part6);
    cudaGetSymbolAddress((void**)&p_xzh,    g_xzh);
    cudaGetSymbolAddress((void**)&p_du,     g_du);
    cudaGetSymbolAddress((void**)&p_uh,     g_uh);
    cudaGetSymbolAddress((void**)&p_xdblh,  g_xdbl_h);
    cudaGetSymbolAddress((void**)&p_yh,     g_yh);
    cudaGetSymbolAddress((void**)&p_xh,     g_xh);
    cudaGetSymbolAddress((void**)&p_w1h,    g_w1h);
    cudaGetSymbolAddress((void**)&p_w3h,    g_w3h);
    cudaGetSymbolAddress((void**)&p_w4h,    g_w4h);
    cudaGetSymbolAddress((void**)&p_w6h,    g_w6h);

    const int smemB = NSTAGE * STAGEB;   // 81920
    cudaFuncSetAttribute((const void*)gemm_h<0, __half>, cudaFuncAttributeMaxDynamicSharedMemorySize, smemB);
    cudaFuncSetAttribute((const void*)gemm_h<0, float>,  cudaFuncAttributeMaxDynamicSharedMemorySize, smemB);
    cudaFuncSetAttribute((const void*)gemm_h<1, __half>, cudaFuncAttributeMaxDynamicSharedMemorySize, smemB);

    // launch 0: cvt x; 1: cvt w1; 2: fused cvt w3/w4/w6
    {
        int nx4 = (BL * D_MODEL) / 4;
        tohalf_kernel<<<(nx4 + 255) / 256, 256>>>(x, p_xh, nx4);
        int nw1_4 = (2 * D_INNER * D_MODEL) / 4;
        tohalf_kernel<<<(nw1_4 + 255) / 256, 256>>>(in_proj_w, p_w1h, nw1_4);
        int n3 = (XDBL_W * D_INNER) / 4;
        int n4 = (D_INNER * DT_RANK) / 4;
        int n6 = (D_MODEL * D_INNER) / 4;
        tohalf3_kernel<<<(n3 + n4 + n6 + 255) / 256, 256>>>(
            x_proj_w, p_w3h, n3, dt_proj_w, p_w4h, n4, out_proj_w, p_w6h, n6);
    }

    // 1) xz = x @ in_proj_w^T [4096,4096] K=1024 -> half  (launch 3 = profiled control)
    gemm_h<0, __half><<<dim3(32, 32), 256, smemB>>>(
        p_xh, D_MODEL, p_w1h, D_MODEL, 2 * D_INNER,
        p_xzh, 2 * D_INNER, nullptr, D_MODEL, 0);

    // 2) u = silu(causal_conv(xi) + cb) -> half
    conv_silu_kernel<<<(BL * D_INNER / 2 + 255) / 256, 256>>>(conv_w, conv_b);
    // 3) x_dbl = u @ x_proj_w^T [4096,96], split-K x8 + reduce (BC interleave) -> half
    gemm_h<0, float><<<dim3(1, 32, SPLITK), 256, smemB>>>(
        p_uh, D_INNER, p_w3h, D_INNER, XDBL_W,
        p_part, XDBL_W, nullptr, D_INNER / SPLITK, (size_t)BL * XDBL_W);
    reduce_split_kernel<<<(BL * XDBL_W + 255) / 256, 256>>>();
    // 4) delta = softplus(dt @ dt_proj_w^T + b); pack (delta,u) -> g_du
    gemm_h<1, __half><<<dim3(16, 32), 256, smemB>>>(
        p_xdblh, XDBL_W, p_w4h, DT_RANK, D_INNER,
        ((__half*)p_du) /*unused*/, D_INNER, dt_proj_b, DT_RANK, 0);
    // 5) selective scan + skip + gate -> half y (148 blocks x 224: one balanced wave)
    scan_kernel<<<148, 224>>>(A_log, Dp);
    // 6) h-partials = y @ out_proj_w^T, split-K x2 [4096,1024]
    gemm_h<0, float><<<dim3(8, 32, SPLITK6), 256, smemB>>>(
        p_yh, D_INNER, p_w6h, D_INNER, D_MODEL,
        p_part6, D_MODEL, nullptr, D_INNER / SPLITK6, (size_t)BL * D_MODEL);
    // 7) fused reduce + residual + LayerNorm -> out
    reduce_ln_kernel<<<BL, 256>>>(x, ln_w, ln_b, out);
}

// round 17
// speedup vs baseline: 1.4986x; 1.1983x over previous
#include <cuda_runtime.h>
#include <cuda_fp16.h>
#include <math.h>
#include <stdint.h>

#define D_MODEL 1024
#define D_INNER 2048
#define D_STATE 16
#define DT_RANK 64
#define NB 2
#define LSEQ 2048
#define BL (NB*LSEQ)            /* 4096 rows total */
#define XDBL_W 96
#define SPLITK 8
#define SPLITK6 2
#define LOG2E 1.4426950408889634f

// ---------------- scratch (device globals) ----------------
__device__ float  g_part[(size_t)SPLITK * BL * XDBL_W];    // GEMM3 split-K partials
__device__ float  g_part6[(size_t)SPLITK6 * BL * D_MODEL]; // GEMM6 split-K partials
// fp16 buffers (16B-aligned for cp.async)
__device__ __align__(16) __half  g_xzh[(size_t)BL * 2 * D_INNER];
__device__ __align__(16) __half2 g_du[(size_t)BL * D_INNER];    // packed (delta, u)
__device__ __align__(16) __half  g_uh[(size_t)BL * D_INNER];
__device__ __align__(16) __half  g_xdbl_h[(size_t)BL * XDBL_W]; // [dt(64)|BC interleaved(32)]
__device__ __align__(16) __half  g_yh[(size_t)BL * D_INNER];
__device__ __align__(16) __half  g_xh[(size_t)BL * D_MODEL];
__device__ __align__(16) __half  g_w1h[(size_t)2 * D_INNER * D_MODEL];
__device__ __align__(16) __half  g_w3h[(size_t)XDBL_W * D_INNER];
__device__ __align__(16) __half  g_w4h[(size_t)D_INNER * DT_RANK];
__device__ __align__(16) __half  g_w6h[(size_t)D_MODEL * D_INNER];

__device__ __forceinline__ void mma_f16(float* d, const uint32_t* a, const uint32_t* b) {
    asm volatile(
        "mma.sync.aligned.m16n8k16.row.col.f32.f16.f16.f32 "
        "{%0,%1,%2,%3}, {%4,%5,%6,%7}, {%8,%9}, {%0,%1,%2,%3};"
        : "+f"(d[0]), "+f"(d[1]), "+f"(d[2]), "+f"(d[3])
        : "r"(a[0]), "r"(a[1]), "r"(a[2]), "r"(a[3]), "r"(b[0]), "r"(b[1]));
}
__device__ __forceinline__ void ldsm4(uint32_t* r, uint32_t addr) {
    asm volatile("ldmatrix.sync.aligned.m8n8.x4.shared.b16 {%0,%1,%2,%3}, [%4];"
                 : "=r"(r[0]), "=r"(r[1]), "=r"(r[2]), "=r"(r[3]) : "r"(addr));
}
__device__ __forceinline__ void cp16(uint32_t dst, const void* src, bool pred) {
    int sz = pred ? 16 : 0;
    asm volatile("cp.async.cg.shared.global [%0], [%1], 16, %2;"
                 :: "r"(dst), "l"(src), "r"(sz) : "memory");
}
#define CP_COMMIT() asm volatile("cp.async.commit_group;" ::: "memory")
#define CP_WAIT(n)  asm volatile("cp.async.wait_group %0;" :: "n"(n) : "memory")

// ================= fp16 mma.sync GEMM, cp.async depth-2 =================
// EPI: 0 plain, 1 softplus+pack(delta,u)->g_du
#define SPITCH_H 40
#define A_HALVES (128 * SPITCH_H)
#define STAGE_HALVES (2 * A_HALVES)
#define STAGEB (STAGE_HALVES * 2)
#define NSTAGE 4

template<int EPI, typename OutT>
__global__ __launch_bounds__(256, 2)
void gemm_h(const __half* __restrict__ A, int lda,
            const __half* __restrict__ Bw, int ldb, int Nact,
            OutT* __restrict__ C, int ldc,
            const float* __restrict__ aux, int K, size_t csplit)
{
    extern __shared__ __half smem[];
    const int tid = threadIdx.x;
    const int wid = tid >> 5;
    const int lane = tid & 31;
    const int g = lane >> 2;
    const int t4 = lane & 3;
    const int warp_m = wid >> 1;
    const int warp_n = wid & 1;
    const int bm = blockIdx.y * 128;
    const int bn = blockIdx.x * 128;

    const int kbase = blockIdx.z * K;
    C += (size_t)blockIdx.z * csplit;

    const int row = tid >> 1;
    const int seg = (tid & 1) << 4;

    const bool bok = (bn + row) < Nact;
    const __half* Ap = A + (size_t)(bm + row) * lda + kbase + seg;
    const __half* Bp = Bw + (size_t)(bn + row) * ldb + kbase + seg;

    uint32_t sbase;
    asm("{ .reg .u64 t; cvta.to.shared.u64 t, %1; cvt.u32.u64 %0, t; }"
        : "=r"(sbase) : "l"(smem));
    const uint32_t dA = sbase + ((uint32_t)row * SPITCH_H + seg) * 2;
    const uint32_t dB = dA + A_HALVES * 2;

    uint32_t aoff[2], boff[4];
#pragma unroll
    for (int mt = 0; mt < 2; mt++)
        aoff[mt] = (((uint32_t)(warp_m * 32 + mt * 16 + (lane & 15))) * SPITCH_H
                    + ((lane >> 4) << 3)) * 2;
#pragma unroll
    for (int nt2 = 0; nt2 < 4; nt2++)
        boff[nt2] = A_HALVES * 2 +
                    (((uint32_t)(warp_n * 64 + nt2 * 16 + (lane & 7) + ((lane >> 4) << 3)))
                     * SPITCH_H + (((lane >> 3) & 1) << 3)) * 2;

    float acc[2][8][4];
#pragma unroll
    for (int mt = 0; mt < 2; mt++)
#pragma unroll
        for (int nt = 0; nt < 8; nt++)
#pragma unroll
            for (int q = 0; q < 4; q++) acc[mt][nt][q] = 0.f;

    const int NC = K >> 5;

    auto issue = [&](int c) {
        const uint32_t so = (uint32_t)(c & (NSTAGE - 1)) * STAGEB;
        const int k0 = c << 5;
        cp16(dA + so,      Ap + k0,     true);
        cp16(dA + so + 16, Ap + k0 + 8, true);
        cp16(dB + so,      Bp + k0,     bok);
        cp16(dB + so + 16, Bp + k0 + 8, bok);
        CP_COMMIT();
    };
    auto compute = [&](int buf) {
        const uint32_t so = sbase + (uint32_t)buf * STAGEB;
#pragma unroll
        for (int ks = 0; ks < 2; ks++) {
            const uint32_t kb = so + ks * 32;
            uint32_t afr[2][4], bfr[4][4];
#pragma unroll
            for (int mt = 0; mt < 2; mt++) ldsm4(afr[mt], kb + aoff[mt]);
#pragma unroll
            for (int nt2 = 0; nt2 < 4; nt2++) ldsm4(bfr[nt2], kb + boff[nt2]);
#pragma unroll
            for (int mt = 0; mt < 2; mt++)
#pragma unroll
                for (int nt2 = 0; nt2 < 4; nt2++) {
                    mma_f16(acc[mt][nt2 * 2],     afr[mt], &bfr[nt2][0]);
                    mma_f16(acc[mt][nt2 * 2 + 1], afr[mt], &bfr[nt2][2]);
                }
        }
    };

    issue(0);
    if (NC > 1) issue(1);

    for (int c = 0; c < NC; c++) {
        if (c + 1 < NC) CP_WAIT(1);
        else            CP_WAIT(0);
        __syncthreads();
        if (c + 2 < NC) issue(c + 2);
        compute(c & (NSTAGE - 1));
    }

#pragma unroll
    for (int mt = 0; mt < 2; mt++) {
        const int r0 = bm + warp_m * 32 + mt * 16 + g;
#pragma unroll
        for (int nt = 0; nt < 8; nt++) {
            const int col = bn + warp_n * 64 + nt * 8 + 2 * t4;
            if (col >= Nact) continue;
#pragma unroll
            for (int hrow = 0; hrow < 2; hrow++) {
                const int r = r0 + hrow * 8;
                float2 v = make_float2(acc[mt][nt][hrow * 2], acc[mt][nt][hrow * 2 + 1]);
                if (EPI == 1) {
                    float2 bs = *(const float2*)(aux + col);
                    v.x += bs.x; v.y += bs.y;
                    v.x = fmaxf(v.x, 0.f) + log1pf(expf(-fabsf(v.x)));
                    v.y = fmaxf(v.y, 0.f) + log1pf(expf(-fabsf(v.y)));
                    __half2 uv = *(const __half2*)(g_uh + (size_t)r * ldc + col);
                    __half2 dd = __floats2half2_rn(v.x, v.y);
                    g_du[(size_t)r * ldc + col]     = __halves2half2(__low2half(dd),  __low2half(uv));
                    g_du[(size_t)r * ldc + col + 1] = __halves2half2(__high2half(dd), __high2half(uv));
                } else {
                    if (sizeof(OutT) == 2) {
                        *(__half2*)((__half*)C + (size_t)r * ldc + col) = __float22half2_rn(v);
                    } else {
                        *(float2*)((float*)C + (size_t)r * ldc + col) = v;
                    }
                }
            }
        }
    }
}

// ---------------- fp32 -> fp16 conversion ----------------
__global__ __launch_bounds__(256)
void tohalf_kernel(const float* __restrict__ src, __half* __restrict__ dst, int n4)
{
    int i = blockIdx.x * blockDim.x + threadIdx.x;
    if (i >= n4) return;
    float4 v = ((const float4*)src)[i];
    ((__half2*)dst)[i * 2]     = __floats2half2_rn(v.x, v.y);
    ((__half2*)dst)[i * 2 + 1] = __floats2half2_rn(v.z, v.w);
}

// ---------------- fused cvt of 3 weight buffers ----------------
__global__ __launch_bounds__(256)
void tohalf3_kernel(const float* __restrict__ s0, __half* __restrict__ d0, int n0_4,
                    const float* __restrict__ s1, __half* __restrict__ d1, int n1_4,
                    const float* __restrict__ s2, __half* __restrict__ d2, int n2_4)
{
    int i = blockIdx.x * blockDim.x + threadIdx.x;
    const float* s; __half* d; int j;
    if (i < n0_4)                { s = s0; d = d0; j = i; }
    else if (i < n0_4 + n1_4)    { s = s1; d = d1; j = i - n0_4; }
    else if (i < n0_4 + n1_4 + n2_4) { s = s2; d = d2; j = i - n0_4 - n1_4; }
    else return;
    float4 v = ((const float4*)s)[j];
    ((__half2*)d)[j * 2]     = __floats2half2_rn(v.x, v.y);
    ((__half2*)d)[j * 2 + 1] = __floats2half2_rn(v.z, v.w);
}

// ---------------- split-K reduce -> half xdbl with BC interleave ----------------
__global__ __launch_bounds__(256)
void reduce_split_kernel()
{
    int idx = blockIdx.x * blockDim.x + threadIdx.x;
    if (idx >= BL * XDBL_W) return;
    float s = 0.f;
#pragma unroll
    for (int k = 0; k < SPLITK; k++)
        s += g_part[(size_t)k * BL * XDBL_W + idx];
    int row = idx / XDBL_W;
    int c = idx - row * XDBL_W;
    int oc;
    if (c < DT_RANK) {
        oc = c;
    } else if (c < DT_RANK + D_STATE) {
        int nb = c - DT_RANK;
        oc = DT_RANK + (nb >> 1) * 4 + (nb & 1);
    } else {
        int nc = c - DT_RANK - D_STATE;
        oc = DT_RANK + (nc >> 1) * 4 + 2 + (nc & 1);
    }
    g_xdbl_h[(size_t)row * XDBL_W + oc] = __float2half_rn(s);
}

// ---------------- causal depthwise conv + bias + SiLU (half2, 2 ch/thread) ----------------
__global__ __launch_bounds__(256)
void conv_silu_kernel(const float* __restrict__ cw, const float* __restrict__ cb)
{
    int idx = blockIdx.x * blockDim.x + threadIdx.x;
    if (idx >= BL * D_INNER / 2) return;
    int dp = idx & (D_INNER / 2 - 1);
    int d = dp << 1;
    int row = idx >> 10;
    int l = row & (LSEQ - 1);

    float4 wa = *(const float4*)(cw + d * 4);
    float4 wb = *(const float4*)(cw + d * 4 + 4);
    float2 bias = *(const float2*)(cb + d);
    float a0 = bias.x, a1 = bias.y;

    const __half2* src = (const __half2*)g_xzh + dp;
#pragma unroll
    for (int j = 0; j < 4; j++) {
        int lj = l - 3 + j;
        if (lj >= 0) {
            float2 v = __half22float2(src[(size_t)(row - 3 + j) * 2048]);
            float w0 = (j == 0) ? wa.x : (j == 1) ? wa.y : (j == 2) ? wa.z : wa.w;
            float w1 = (j == 0) ? wb.x : (j == 1) ? wb.y : (j == 2) ? wb.z : wb.w;
            a0 = fmaf(v.x, w0, a0);
            a1 = fmaf(v.y, w1, a1);
        }
    }
    float s0 = a0 / (1.f + __expf(-a0));
    float s1 = a1 / (1.f + __expf(-a1));
    ((__half2*)g_uh)[idx] = __floats2half2_rn(s0, s1);
}

// ---------------- selective scan: 8 lanes/channel, 2 states/lane ----------------
// 148 blocks x 224 threads, single balanced wave. Ping-pong copy-free.
// proc_pair: two 4-step h-chains back-to-back, then 3 levels x 8-wide shfl batch.
// exp2 precompute (A*log2e) and fast silu.
__global__ __launch_bounds__(224)
void scan_kernel(const float* __restrict__ A_log, const float* __restrict__ Dp)
{
    const int tid = threadIdx.x;
    const int ch_raw = blockIdx.x * 28 + (tid >> 3);
    const bool active = ch_raw < BL;
    const int ch = active ? ch_raw : (BL - 1);
    const int b = ch >> 11;
    const int d = ch & (D_INNER - 1);
    const int ls = tid & 7;
    const int n0 = ls << 1;

    const float A0L = -expf(A_log[d * D_STATE + n0])     * LOG2E;
    const float A1L = -expf(A_log[d * D_STATE + n0 + 1]) * LOG2E;
    const float Dd = Dp[d];

    float h0 = 0.f, h1 = 0.f;
    const __half* xd = g_xdbl_h + (size_t)b * LSEQ * XDBL_W + DT_RANK + ls * 4;
    const size_t base2 = (size_t)b * LSEQ * D_INNER + d;
    const size_t basez = (size_t)b * LSEQ * (2 * D_INNER) + D_INNER + d;

    auto load_group = [&](int l, float* D_, float* U_, float* Z_, float2* B_, float2* C_) {
#pragma unroll
        for (int j = 0; j < 4; j++) {
            __half2 du = g_du[base2 + (size_t)(l + j) * D_INNER];
            float2 f = __half22float2(du);
            D_[j] = f.x;
            U_[j] = f.y;
        }
        if (ls == 0) {
#pragma unroll
            for (int j = 0; j < 4; j++)
                Z_[j] = __half2float(g_xzh[basez + (size_t)(l + j) * (2 * D_INNER)]);
        }
#pragma unroll
        for (int j = 0; j < 4; j++) {
            uint2 bc = *(const uint2*)(xd + (size_t)(l + j) * XDBL_W);
            B_[j] = __half22float2(*(const __half2*)&bc.x);
            C_[j] = __half22float2(*(const __half2*)&bc.y);
        }
    };

    // fused pair: 8 recurrence steps, 8-wide shfl levels, 8 stores
    auto proc_pair = [&](int l0,
                         const float* D1, const float* U1, const float* Z1,
                         const float2* B1, const float2* C1,
                         const float* D2, const float* U2, const float* Z2,
                         const float2* B2, const float2* C2) {
        float yp[8];
#pragma unroll
        for (int j = 0; j < 4; j++) {
            float e0 = exp2f(D1[j] * A0L);
            float e1 = exp2f(D1[j] * A1L);
            float du = D1[j] * U1[j];
            h0 = fmaf(e0, h0, du * B1[j].x);
            h1 = fmaf(e1, h1, du * B1[j].y);
            yp[j] = fmaf(h0, C1[j].x, h1 * C1[j].y);
        }
#pragma unroll
        for (int j = 0; j < 4; j++) {
            float e0 = exp2f(D2[j] * A0L);
            float e1 = exp2f(D2[j] * A1L);
            float du = D2[j] * U2[j];
            h0 = fmaf(e0, h0, du * B2[j].x);
            h1 = fmaf(e1, h1, du * B2[j].y);
            yp[4 + j] = fmaf(h0, C2[j].x, h1 * C2[j].y);
        }
#pragma unroll
        for (int j = 0; j < 8; j++) yp[j] += __shfl_xor_sync(0xffffffffu, yp[j], 1);
#pragma unroll
        for (int j = 0; j < 8; j++) yp[j] += __shfl_xor_sync(0xffffffffu, yp[j], 2);
#pragma unroll
        for (int j = 0; j < 8; j++) yp[j] += __shfl_xor_sync(0xffffffffu, yp[j], 4);
        if (ls == 0 && active) {
#pragma unroll
            for (int j = 0; j < 4; j++) {
                float z = Z1[j];
                float sz = __fdividef(z, 1.f + exp2f(z * -LOG2E));
                g_yh[base2 + (size_t)(l0 + j) * D_INNER] =
                    __float2half_rn(fmaf(U1[j], Dd, yp[j]) * sz);
            }
#pragma unroll
            for (int j = 0; j < 4; j++) {
                float z = Z2[j];
                float sz = __fdividef(z, 1.f + exp2f(z * -LOG2E));
                g_yh[base2 + (size_t)(l0 + 4 + j) * D_INNER] =
                    __float2half_rn(fmaf(U2[j], Dd, yp[4 + j]) * sz);
            }
        }
    };

    float aD[4], aU[4], aZ[4]; float2 aB[4], aC[4];
    float bD[4], bU[4], bZ[4]; float2 bB[4], bC[4];
    float tD[4], tU[4], tZ[4]; float2 tB[4], tC[4];
    float sD[4], sU[4], sZ[4]; float2 sB[4], sC[4];

    load_group(0, aD, aU, aZ, aB, aC);
    load_group(4, bD, bU, bZ, bB, bC);

    for (int l0 = 0; l0 < LSEQ; l0 += 16) {
        if (l0 + 8  < LSEQ) load_group(l0 + 8,  tD, tU, tZ, tB, tC);
        if (l0 + 12 < LSEQ) load_group(l0 + 12, sD, sU, sZ, sB, sC);
        proc_pair(l0, aD, aU, aZ, aB, aC, bD, bU, bZ, bB, bC);
        if (l0 + 16 < LSEQ) {
            load_group(l0 + 16, aD, aU, aZ, aB, aC);
            load_group(l0 + 20, bD, bU, bZ, bB, bC);
        }
        proc_pair(l0 + 8, tD, tU, tZ, tB, tC, sD, sU, sZ, sB, sC);
    }
}

// ---------------- fused GEMM6-reduce + residual + LayerNorm ----------------
__global__ __launch_bounds__(256)
void reduce_ln_kernel(const float* __restrict__ x,
                      const float* __restrict__ lnw, const float* __restrict__ lnb,
                      float* __restrict__ out)
{
    int row = blockIdx.x;
    int tid = threadIdx.x;
    const float* p0 = g_part6 + (size_t)row * D_MODEL;
    const float* p1 = g_part6 + (size_t)BL * D_MODEL + (size_t)row * D_MODEL;
    const float* xr = x + (size_t)row * D_MODEL;

    float v[4];
    float s = 0.f, sq = 0.f;
#pragma unroll
    for (int i = 0; i < 4; i++) {
        int c = tid + i * 256;
        v[i] = p0[c] + p1[c] + xr[c];
        s += v[i];
        sq += v[i] * v[i];
    }
#pragma unroll
    for (int off = 16; off; off >>= 1) {
        s += __shfl_xor_sync(0xffffffffu, s, off);
        sq += __shfl_xor_sync(0xffffffffu, sq, off);
    }
    __shared__ float ss[8], ssq[8];
    __shared__ float mu_s, rs_s;
    if ((tid & 31) == 0) { ss[tid >> 5] = s; ssq[tid >> 5] = sq; }
    __syncthreads();
    if (tid == 0) {
        float S = 0.f, SQ = 0.f;
#pragma unroll
        for (int i = 0; i < 8; i++) { S += ss[i]; SQ += ssq[i]; }
        float mu = S * (1.f / D_MODEL);
        float var = SQ * (1.f / D_MODEL) - mu * mu;
        mu_s = mu;
        rs_s = rsqrtf(var + 1e-5f);
    }
    __syncthreads();
    float mu = mu_s, rs = rs_s;
#pragma unroll
    for (int i = 0; i < 4; i++) {
        int c = tid + i * 256;
        out[(size_t)row * D_MODEL + c] = (v[i] - mu) * rs * lnw[c] + lnb[c];
    }
}

// ---------------- host launch ----------------
extern "C" void kernel_launch(void* const* d_in, const int* in_sizes, int n_in,
                              void* d_out, int out_size)
{
    const float* x          = (const float*)d_in[0];
    const float* in_proj_w  = (const float*)d_in[1];
    const float* conv_w     = (const float*)d_in[2];
    const float* conv_b     = (const float*)d_in[3];
    const float* x_proj_w   = (const float*)d_in[4];
    const float* dt_proj_w  = (const float*)d_in[5];
    const float* dt_proj_b  = (const float*)d_in[6];
    const float* A_log      = (const float*)d_in[7];
    const float* Dp         = (const float*)d_in[8];
    const float* out_proj_w = (const float*)d_in[9];
    const float* ln_w       = (const float*)d_in[10];
    const float* ln_b       = (const float*)d_in[11];
    float* out = (float*)d_out;

    float *p_part, *p_part6;
    __half *p_xzh, *p_uh, *p_xdblh, *p_yh, *p_xh;
    __half *p_w1h, *p_w3h, *p_w4h, *p_w6h;
    __half2 *p_du;
    cudaGetSymbolAddress((void**)&p_part,   g_part);
    cudaGetSymbolAddress((void**)&p_part6,  g_part6);
    cudaGetSymbolAddress((void**)&p_xzh,    g_xzh);
    cudaGetSymbolAddress((void**)&p_du,     g_du);
    cudaGetSymbolAddress((void**)&p_uh,     g_uh);
    cudaGetSymbolAddress((void**)&p_xdblh,  g_xdbl_h);
    cudaGetSymbolAddress((void**)&p_yh,     g_yh);
    cudaGetSymbolAddress((void**)&p_xh,     g_xh);
    cudaGetSymbolAddress((void**)&p_w1h,    g_w1h);
    cudaGetSymbolAddress((void**)&p_w3h,    g_w3h);
    cudaGetSymbolAddress((void**)&p_w4h,    g_w4h);
    cudaGetSymbolAddress((void**)&p_w6h,    g_w6h);

    const int smemB = NSTAGE * STAGEB;   // 81920
    cudaFuncSetAttribute((const void*)gemm_h<0, __half>, cudaFuncAttributeMaxDynamicSharedMemorySize, smemB);
    cudaFuncSetAttribute((const void*)gemm_h<0, float>,  cudaFuncAttributeMaxDynamicSharedMemorySize, smemB);
    cudaFuncSetAttribute((const void*)gemm_h<1, __half>, cudaFuncAttributeMaxDynamicSharedMemorySize, smemB);

    // launch 0: cvt x; 1: cvt w1; 2: fused cvt w3/w4/w6
    {
        int nx4 = (BL * D_MODEL) / 4;
        tohalf_kernel<<<(nx4 + 255) / 256, 256>>>(x, p_xh, nx4);
        int nw1_4 = (2 * D_INNER * D_MODEL) / 4;
        tohalf_kernel<<<(nw1_4 + 255) / 256, 256>>>(in_proj_w, p_w1h, nw1_4);
        int n3 = (XDBL_W * D_INNER) / 4;
        int n4 = (D_INNER * DT_RANK) / 4;
        int n6 = (D_MODEL * D_INNER) / 4;
        tohalf3_kernel<<<(n3 + n4 + n6 + 255) / 256, 256>>>(
            x_proj_w, p_w3h, n3, dt_proj_w, p_w4h, n4, out_proj_w, p_w6h, n6);
    }

    // 1) xz = x @ in_proj_w^T [4096,4096] K=1024 -> half  (launch 3 = profiled control)
    gemm_h<0, __half><<<dim3(32, 32), 256, smemB>>>(
        p_xh, D_MODEL, p_w1h, D_MODEL, 2 * D_INNER,
        p_xzh, 2 * D_INNER, nullptr, D_MODEL, 0);

    // 2) u = silu(causal_conv(xi) + cb) -> half
    conv_silu_kernel<<<(BL * D_INNER / 2 + 255) / 256, 256>>>(conv_w, conv_b);
    // 3) x_dbl = u @ x_proj_w^T [4096,96], split-K x8 + reduce (BC interleave) -> half
    gemm_h<0, float><<<dim3(1, 32, SPLITK), 256, smemB>>>(
        p_uh, D_INNER, p_w3h, D_INNER, XDBL_W,
        p_part, XDBL_W, nullptr, D_INNER / SPLITK, (size_t)BL * XDBL_W);
    reduce_split_kernel<<<(BL * XDBL_W + 255) / 256, 256>>>();
    // 4) delta = softplus(dt @ dt_proj_w^T + b); pack (delta,u) -> g_du
    gemm_h<1, __half><<<dim3(16, 32), 256, smemB>>>(
        p_xdblh, XDBL_W, p_w4h, DT_RANK, D_INNER,
        ((__half*)p_du) /*unused*/, D_INNER, dt_proj_b, DT_RANK, 0);
    // 5) selective scan + skip + gate -> half y
    scan_kernel<<<148, 224>>>(A_log, Dp);
    // 6) h-partials = y @ out_proj_w^T, split-K x2 [4096,1024]
    gemm_h<0, float><<<dim3(8, 32, SPLITK6), 256, smemB>>>(
        p_yh, D_INNER, p_w6h, D_INNER, D_MODEL,
        p_part6, D_MODEL, nullptr, D_INNER / SPLITK6, (size_t)BL * D_MODEL);
    // 7) fused reduce + residual + LayerNorm -> out
    reduce_ln_kernel<<<BL, 256>>>(x, ln_w, ln_b, out);
}